// round 8
// baseline (speedup 1.0000x reference)
#include <cuda_runtime.h>
#include <cuda_bf16.h>
#include <cstdint>

#define B    32
#define NN   2000
#define TD   384
#define E    64
#define TT   24
#define DD   16
#define NNP  2048

#define BR   64
#define BC   32
#define NTK  63

// ---- attn smem byte layout
#define OFF_K  0           // 2 stages x (2 splits x 32 rows x 144B) = 18432
#define KTILE  9216
#define KSPLIT 4608
#define OFF_V  18432       // 2 stages x (2 splits x 384 rows x 80B) = 122880
#define VTILE  61440
#define VSPLIT 30720
#define OFF_PH 141312      // 64 x 80B
#define OFF_PL 146432
#define OFF_L  151552      // 128 floats
#define SMEM_ATT 152064
#define OST 392            // epilogue stage stride (floats), reuses OFF_V area

typedef unsigned long long u64;

__device__ __align__(16) __nv_bfloat16 g_qh[B*NN*E];
__device__ __align__(16) __nv_bfloat16 g_ql[B*NN*E];
__device__ __align__(16) __nv_bfloat16 g_kh[B*NN*E];
__device__ __align__(16) __nv_bfloat16 g_kl[B*NN*E];
__device__ __align__(16) __nv_bfloat16 g_vth[TD*NNP];
__device__ __align__(16) __nv_bfloat16 g_vtl[TD*NNP];

// =================== helpers ===================
__device__ __forceinline__ uint32_t cvta_s(const void* p){
    return (uint32_t)__cvta_generic_to_shared(p);
}
__device__ __forceinline__ void cpa16(uint32_t d, const void* s){
    asm volatile("cp.async.cg.shared.global [%0],[%1],16;" :: "r"(d), "l"(s));
}
#define CP_COMMIT() asm volatile("cp.async.commit_group;")

__device__ __forceinline__ void mma16816(float* d, const uint32_t* a, const uint32_t* b){
    asm volatile("mma.sync.aligned.m16n8k16.row.col.f32.bf16.bf16.f32 "
        "{%0,%1,%2,%3},{%4,%5,%6,%7},{%8,%9},{%0,%1,%2,%3};"
        : "+f"(d[0]), "+f"(d[1]), "+f"(d[2]), "+f"(d[3])
        : "r"(a[0]), "r"(a[1]), "r"(a[2]), "r"(a[3]), "r"(b[0]), "r"(b[1]));
}
__device__ __forceinline__ void ldsm4(uint32_t &r0, uint32_t &r1, uint32_t &r2, uint32_t &r3,
                                      uint32_t addr){
    asm volatile("ldmatrix.sync.aligned.m8n8.x4.shared.b16 {%0,%1,%2,%3}, [%4];"
        : "=r"(r0), "=r"(r1), "=r"(r2), "=r"(r3) : "r"(addr));
}

__device__ __forceinline__ float fexp(float x){   // valid |x| <= ~3
    float t = x * 1.4426950408889634f;
    float c = t + 12582912.f;
    int k = __float_as_int(c) - 0x4B400000;
    float f = t - (c - 12582912.f);
    float z = f * 0.6931471805599453f;
    float p = fmaf(z, 0.0083333333f, 0.0416666667f);
    p = fmaf(p, z, 0.1666666667f);
    p = fmaf(p, z, 0.5f);
    p = fmaf(p, z, 1.0f);
    p = fmaf(p, z, 1.0f);
    return __int_as_float(__float_as_int(p) + (k << 23));
}
__device__ __forceinline__ int imin(int a, int b){ return a < b ? a : b; }
__device__ __forceinline__ uint32_t pkbf(float a, float b){
    __nv_bfloat16 h0 = __float2bfloat16(a), h1 = __float2bfloat16(b);
    return (uint32_t)__bfloat16_as_ushort(h0) | ((uint32_t)__bfloat16_as_ushort(h1) << 16);
}
__device__ __forceinline__ u64 pk2(float a, float b){
    u64 r; asm("mov.b64 %0,{%1,%2};" : "=l"(r) : "f"(a), "f"(b)); return r;
}
__device__ __forceinline__ void ff2(u64 &d, u64 a, u64 b){
    asm("fma.rn.f32x2 %0,%1,%2,%0;" : "+l"(d) : "l"(a), "l"(b));
}
__device__ __forceinline__ float2 up2(u64 v){
    float2 r; asm("mov.b64 {%0,%1},%2;" : "=f"(r.x), "=f"(r.y) : "l"(v)); return r;
}

// ============================================================
// prep: V transposed [col][NNP kv] + bf16 hi/lo split
// ============================================================
__global__ __launch_bounds__(256) void prep_vt(const float* __restrict__ normal){
    int idx = blockIdx.x*256 + threadIdx.x;
    if (idx < TD*NNP){
        int n = idx >> 11, kv = idx & (NNP-1);
        float v = (kv < NN) ? normal[(size_t)kv*TD + n] : 0.f;
        __nv_bfloat16 h = __float2bfloat16(v);
        g_vth[idx] = h;
        g_vtl[idx] = __float2bfloat16(v - __bfloat162float(h));
    }
}

// ============================================================
// Kernel 1: q1/k1 = LN(xf@W + b) -> bf16 hi/lo splits
// ============================================================
#define K1_ROWS 64
#define W_CH 32
#define N_CH (TD / W_CH)
#define K1_XS 0
#define K1_WS 24576
#define K1_QK 32768
#define K1_MU 40960
#define K1_RS 41088
#define K1_SM_BYTES (41216*4)

__device__ __forceinline__ void k1_prefetch_w(float* ws, int tid, int c,
        const float* Wq, const float* Wk)
{
    if (c < N_CH) {
        float* dst = ws + (c & 1) * (W_CH * 128);
        int c0 = c * W_CH;
#pragma unroll
        for (int j = 0; j < 2; j++) {
            int idx = tid + j*512;
            int row = idx >> 5, c4 = idx & 31;
            const float* src = (c4 < 16)
                ? (Wq + (size_t)(c0 + row)*E + c4*4)
                : (Wk + (size_t)(c0 + row)*E + (c4 - 16)*4);
            cpa16(cvta_s(dst + row*128 + ((c4 < 16) ? c4*4 : 64 + (c4-16)*4)), src);
        }
    }
    CP_COMMIT();
}

__global__ __launch_bounds__(512, 1) void qk_ln_kernel(
    const float* __restrict__ x,
    const float* __restrict__ Wq, const float* __restrict__ bq,
    const float* __restrict__ Wk, const float* __restrict__ bk,
    const float* __restrict__ g0, const float* __restrict__ beta0,
    const float* __restrict__ g1, const float* __restrict__ beta1)
{
    extern __shared__ float sm1[];
    float* xs = sm1 + K1_XS;
    float* ws = sm1 + K1_WS;
    float* qk = sm1 + K1_QK;
    float* mu_sh = sm1 + K1_MU;
    float* rs_sh = sm1 + K1_RS;
    const int tid = threadIdx.x;
    const long base = (long)blockIdx.x * K1_ROWS;

    k1_prefetch_w(ws, tid, 0, Wq, Wk);
    k1_prefetch_w(ws, tid, 1, Wq, Wk);

    const float4* xp4 = (const float4*)(x + base*TD);
#pragma unroll
    for (int i = 0; i < 12; i++) ((float4*)xs)[tid + i*512] = xp4[tid + i*512];

    const int col = tid & 63;
    const int grp = tid >> 6;
    const int isK = grp >> 2;
    const int r0  = (grp & 3) * 16;
    const int wcol = isK*64 + col;

    u64 acc2[16];
#pragma unroll
    for (int r = 0; r < 16; r++) acc2[r] = 0ull;

    for (int c = 0; c < N_CH; c++) {
        const float* wb = ws + (c & 1) * (W_CH * 128);
        asm volatile("cp.async.wait_group 1;");
        __syncthreads();
#pragma unroll
        for (int i4l = 0; i4l < W_CH/4; i4l++) {
            int i4 = c*(W_CH/4) + i4l;
            u64 wa = pk2(wb[(i4l*4+0)*128+wcol], wb[(i4l*4+1)*128+wcol]);
            u64 wbp = pk2(wb[(i4l*4+2)*128+wcol], wb[(i4l*4+3)*128+wcol]);
#pragma unroll
            for (int r = 0; r < 16; r++) {
                ulonglong2 xv = ((const ulonglong2*)(xs + (r0 + r)*TD))[i4];
                ff2(acc2[r], xv.x, wa);
                ff2(acc2[r], xv.y, wbp);
            }
        }
        __syncthreads();
        k1_prefetch_w(ws, tid, c + 2, Wq, Wk);
    }

    const float bias = isK ? bk[col] : bq[col];
#pragma unroll
    for (int r = 0; r < 16; r++) {
        float2 f = up2(acc2[r]);
        qk[(r0 + r)*128 + isK*64 + col] = f.x + f.y + bias;
    }
    __syncthreads();

    if (tid < 128) {
        int r = tid & 63, h = tid >> 6;
        const float* v = qk + r*128 + h*64;
        float s = 0.f, s2 = 0.f;
#pragma unroll
        for (int j = 0; j < 64; j++) { float t = v[(j + r) & 63]; s += t; s2 += t*t; }
        float mu = s * (1.f/64.f);
        mu_sh[tid] = mu;
        rs_sh[tid] = rsqrtf(s2*(1.f/64.f) - mu*mu + 1e-5f);
    }
    __syncthreads();

    const float gg = isK ? g1[col] : g0[col];
    const float bb = isK ? beta1[col] : beta0[col];
    __nv_bfloat16* __restrict__ oh = isK ? g_kh : g_qh;
    __nv_bfloat16* __restrict__ ol = isK ? g_kl : g_ql;
#pragma unroll
    for (int r = 0; r < 16; r++) {
        float mu = mu_sh[isK*64 + r0 + r], rs = rs_sh[isK*64 + r0 + r];
        float val = (qk[(r0 + r)*128 + isK*64 + col] - mu) * rs * gg + bb;
        __nv_bfloat16 h = __float2bfloat16(val);
        size_t o = (size_t)(base + r0 + r)*E + col;
        oh[o] = h;
        ol[o] = __float2bfloat16(val - __bfloat162float(h));
    }
}

// ============================================================
// Kernel 2: warp-level bf16 mma.sync flash attention (hi/lo split)
// ldmatrix.x4 for all K/V/P fragments.
// ============================================================
__device__ __forceinline__ void att_prefetch(char* smem, int tid, int t, int b){
    if (t < NTK){
        int st = t & 1;
#pragma unroll
        for (int j = 0; j < 2; j++){            // K: 512 chunks
            int c = tid + j*256;
            int split = c >> 8, rem = c & 255;
            int kv = rem >> 3, ch = rem & 7;
            int g = imin(t*BC + kv, NN-1);
            const __nv_bfloat16* src = (split ? g_kl : g_kh) + ((size_t)b*NN + g)*E + ch*8;
            cpa16(cvta_s(smem + OFF_K + st*KTILE + split*KSPLIT + kv*144 + ch*16), src);
        }
#pragma unroll
        for (int j = 0; j < 12; j++){           // V: 3072 chunks
            int c = tid + j*256;
            int split = (c >= 1536) ? 1 : 0;
            int rem = c - split*1536;
            int col = rem >> 2, ch = rem & 3;
            const __nv_bfloat16* src = (split ? g_vtl : g_vth) + (size_t)col*NNP + t*BC + ch*8;
            cpa16(cvta_s(smem + OFF_V + st*VTILE + split*VSPLIT + col*80 + ch*16), src);
        }
    }
    CP_COMMIT();
}

__global__ __launch_bounds__(256, 1) void attn_mma(
    const float* __restrict__ x,
    const float* __restrict__ Win,
    float* __restrict__ out)
{
    extern __shared__ char smem[];
    const int tid = threadIdx.x;
    const int wid = tid >> 5, lane = tid & 31;
    const int gid = lane >> 2, tig = lane & 3;
    const int rg = wid >> 1, cg = wid & 1;
    const int b = blockIdx.y;
    const int n0 = blockIdx.x * BR;
    const int r0 = rg * 16;
    const float scale = 0.022360679774997897f;   // 1/sqrt(2000)
    const uint32_t smb = cvta_s(smem);

    // ---- thread-invariant ldmatrix base addresses
    // V (B-frag): matrices (h,k0),(h,k8),(lo,k0),(lo,k8); rows = out-col
    const uint32_t vb_t = smb + OFF_V + ((lane & 16) ? VSPLIT : 0u)
                        + (uint32_t)((cg*192 + (lane & 7))*80) + ((lane >> 3) & 1)*16;
    // K (B-frag): rows = kv
    const uint32_t kb_t = smb + OFF_K + ((lane & 16) ? KSPLIT : 0u)
                        + (uint32_t)((cg*16 + (lane & 7))*144) + ((lane >> 3) & 1)*16;
    // P (A-frag): matrices (r0..7,k0),(r8..15,k0),(r0..7,k8),(r8..15,k8)
    const uint32_t pb_h = smb + OFF_PH
                        + (uint32_t)((r0 + ((lane >> 3) & 1)*8 + (lane & 7))*80)
                        + ((lane & 16) ? 16u : 0u);
    const uint32_t pb_l = pb_h + (OFF_PL - OFF_PH);

    // ---- Q fragments hoisted into registers for the whole kernel
    uint32_t aqh[4][4], aql[4][4];
    {
        int nA = imin(n0 + r0 + gid, NN-1);
        int nB = imin(n0 + r0 + gid + 8, NN-1);
        const uint32_t* qh = (const uint32_t*)(g_qh + (size_t)b*NN*E);
        const uint32_t* ql = (const uint32_t*)(g_ql + (size_t)b*NN*E);
#pragma unroll
        for (int ks = 0; ks < 4; ks++){
            int c0 = ks*8 + tig;
            aqh[ks][0] = qh[nA*32 + c0];     aqh[ks][1] = qh[nB*32 + c0];
            aqh[ks][2] = qh[nA*32 + c0 + 4]; aqh[ks][3] = qh[nB*32 + c0 + 4];
            aql[ks][0] = ql[nA*32 + c0];     aql[ks][1] = ql[nB*32 + c0];
            aql[ks][2] = ql[nA*32 + c0 + 4]; aql[ks][3] = ql[nB*32 + c0 + 4];
        }
    }

    att_prefetch(smem, tid, 0, b);
    att_prefetch(smem, tid, 1, b);

    float dacc[24][4];
#pragma unroll
    for (int nt = 0; nt < 24; nt++)
#pragma unroll
        for (int c = 0; c < 4; c++) dacc[nt][c] = 0.f;
    float lA = 0.f, lB = 0.f;

    uint32_t* ph = (uint32_t*)(smem + OFF_PH);
    uint32_t* pl = (uint32_t*)(smem + OFF_PL);

    for (int t = 0; t < NTK; t++){
        const uint32_t stK = (t & 1) ? KTILE : 0u;
        const uint32_t stV = (t & 1) ? VTILE : 0u;
        asm volatile("cp.async.wait_group 1;");
        __syncthreads();

        // ---- S = Qh*Kh + Qh*Kl + Ql*Kh (per warp: 2 n-tiles)
        float sacc[2][4];
#pragma unroll
        for (int nt = 0; nt < 2; nt++)
#pragma unroll
            for (int c = 0; c < 4; c++) sacc[nt][c] = 0.f;
#pragma unroll
        for (int nt = 0; nt < 2; nt++){
            uint32_t kbase = kb_t + stK + nt*1152;
#pragma unroll
            for (int ks = 0; ks < 4; ks++){
                uint32_t bh[2], bl[2];
                ldsm4(bh[0], bh[1], bl[0], bl[1], kbase + ks*32);
                mma16816(sacc[nt], aqh[ks], bh);
                mma16816(sacc[nt], aqh[ks], bl);
                mma16816(sacc[nt], aql[ks], bh);
            }
        }

        // ---- exp + split + store P hi/lo
#pragma unroll
        for (int nt = 0; nt < 2; nt++){
            int colg = t*BC + cg*16 + nt*8 + tig*2;
            bool m0 = colg < NN, m1 = (colg + 1) < NN;
            float p0 = m0 ? fexp(sacc[nt][0]*scale) : 0.f;
            float p1 = m1 ? fexp(sacc[nt][1]*scale) : 0.f;
            float p2 = m0 ? fexp(sacc[nt][2]*scale) : 0.f;
            float p3 = m1 ? fexp(sacc[nt][3]*scale) : 0.f;
            lA += p0 + p1; lB += p2 + p3;
            float h0 = __bfloat162float(__float2bfloat16(p0));
            float h1 = __bfloat162float(__float2bfloat16(p1));
            float h2 = __bfloat162float(__float2bfloat16(p2));
            float h3 = __bfloat162float(__float2bfloat16(p3));
            int wa = (r0 + gid)*20 + cg*8 + nt*4 + tig;
            int wb = (r0 + gid + 8)*20 + cg*8 + nt*4 + tig;
            ph[wa] = pkbf(h0, h1);
            ph[wb] = pkbf(h2, h3);
            pl[wa] = pkbf(p0 - h0, p1 - h1);
            pl[wb] = pkbf(p2 - h2, p3 - h3);
        }
        __syncthreads();

        // ---- PV: dacc += Ph*Vh + Ph*Vl + Pl*Vh (24 n-tiles x 2 k-steps)
#pragma unroll
        for (int ks = 0; ks < 2; ks++){
            uint32_t pah[4], pal[4];
            ldsm4(pah[0], pah[1], pah[2], pah[3], pb_h + ks*32);
            ldsm4(pal[0], pal[1], pal[2], pal[3], pb_l + ks*32);
            uint32_t vbase = vb_t + stV + ks*32;
#pragma unroll
            for (int nt = 0; nt < 24; nt++){
                uint32_t bh[2], bl[2];
                ldsm4(bh[0], bh[1], bl[0], bl[1], vbase + nt*640);
                mma16816(dacc[nt], pah, bh);
                mma16816(dacc[nt], pah, bl);
                mma16816(dacc[nt], pal, bh);
            }
        }
        __syncthreads();
        att_prefetch(smem, tid, t + 2, b);
    }

    // ---- l reduction
    lA += __shfl_xor_sync(0xffffffffu, lA, 1);
    lA += __shfl_xor_sync(0xffffffffu, lA, 2);
    lB += __shfl_xor_sync(0xffffffffu, lB, 1);
    lB += __shfl_xor_sync(0xffffffffu, lB, 2);
    float* l_s = (float*)(smem + OFF_L);
    if (tig == 0){
        l_s[cg*64 + r0 + gid]     = lA;
        l_s[cg*64 + r0 + gid + 8] = lB;
    }
    __syncthreads();
    float invA = 1.f / (l_s[r0 + gid]     + l_s[64 + r0 + gid]);
    float invB = 1.f / (l_s[r0 + gid + 8] + l_s[64 + r0 + gid + 8]);

    // ---- stage data = dacc / l into OFF_V area (stride OST)
    float* stage = (float*)(smem + OFF_V);
#pragma unroll
    for (int nt = 0; nt < 24; nt++){
        int col = cg*192 + nt*8 + tig*2;
        float* sa = stage + (r0 + gid)*OST + col;
        sa[0] = dacc[nt][0]*invA; sa[1] = dacc[nt][1]*invA;
        float* sb = stage + (r0 + gid + 8)*OST + col;
        sb[0] = dacc[nt][2]*invB; sb[1] = dacc[nt][3]*invB;
    }
    __syncthreads();

    // ---- RPPsAtt weights per row
    float* w_s = (float*)(smem + OFF_PH);   // 64*24 floats
    if (tid < BR){
        int n = n0 + tid;
        if (n < NN){
            const float* xl = x + ((size_t)b*NN + n)*TD + (TT - 1)*DD;
            float q16[DD];
#pragma unroll
            for (int dp = 0; dp < DD; dp++){
                float s = 0.f;
#pragma unroll
                for (int d = 0; d < DD; d++) s = fmaf(xl[d], Win[d*DD + dp], s);
                q16[dp] = s;
            }
            const float* row = stage + tid*OST;
            float att[TT]; float mx = -1e30f;
#pragma unroll
            for (int t2 = 0; t2 < TT; t2++){
                float s = 0.f;
#pragma unroll
                for (int d = 0; d < DD; d++) s = fmaf(q16[d], row[t2*DD + d], s);
                att[t2] = s; mx = fmaxf(mx, s);
            }
            float se = 0.f;
#pragma unroll
            for (int t2 = 0; t2 < TT; t2++){ float e = __expf(att[t2] - mx); att[t2] = e; se += e; }
            float si = 1.f / se;
#pragma unroll
            for (int t2 = 0; t2 < TT; t2++) w_s[tid*TT + t2] = att[t2] * si;
        }
    }
    __syncthreads();

    // ---- out = data + weight[..., None]
    int nrows = NN - n0; if (nrows > BR) nrows = BR;
    float4* outp = (float4*)(out + ((size_t)b*NN + n0)*TD);
    for (int i = tid; i < nrows*96; i += 256){
        int r = i / 96, c4 = i - r*96;
        const float* sr = stage + r*OST + c4*4;
        float w = w_s[r*TT + (c4 >> 2)];
        float4 v;
        v.x = sr[0] + w; v.y = sr[1] + w; v.z = sr[2] + w; v.w = sr[3] + w;
        outp[i] = v;
    }
}

// ============================================================
extern "C" void kernel_launch(void* const* d_in, const int* in_sizes, int n_in,
                              void* d_out, int out_size)
{
    (void)in_sizes; (void)n_in; (void)out_size;
    const float* x     = (const float*)d_in[0];
    const float* Wq    = (const float*)d_in[1];
    const float* bq    = (const float*)d_in[2];
    const float* Wk    = (const float*)d_in[3];
    const float* bk    = (const float*)d_in[4];
    const float* g0    = (const float*)d_in[5];
    const float* beta0 = (const float*)d_in[6];
    const float* g1    = (const float*)d_in[7];
    const float* beta1 = (const float*)d_in[8];
    const float* nrm   = (const float*)d_in[9];
    const float* Win   = (const float*)d_in[10];
    float* out = (float*)d_out;

    cudaFuncSetAttribute(qk_ln_kernel, cudaFuncAttributeMaxDynamicSharedMemorySize, K1_SM_BYTES);
    cudaFuncSetAttribute(attn_mma,     cudaFuncAttributeMaxDynamicSharedMemorySize, SMEM_ATT);

    prep_vt<<<(TD*NNP + 255)/256, 256>>>(nrm);
    qk_ln_kernel<<<(B*NN)/K1_ROWS, 512, K1_SM_BYTES>>>(x, Wq, bq, Wk, bk, g0, beta0, g1, beta1);

    dim3 grid((NN + BR - 1)/BR, B);
    attn_mma<<<grid, 256, SMEM_ATT>>>(x, Win, out);
}

// round 9
// speedup vs baseline: 1.0797x; 1.0797x over previous
#include <cuda_runtime.h>
#include <cuda_bf16.h>
#include <cstdint>

#define B    32
#define NN   2000
#define TD   384
#define E    64
#define TT   24
#define DD   16
#define NNP  2048

#define BR   64
#define BC   32
#define NTK  63

// ---- attn smem byte layout
#define OFF_K  0           // 2 stages x (2 splits x 32 rows x 144B) = 18432
#define KTILE  9216
#define KSPLIT 4608
#define OFF_V  18432       // 2 stages x (2 splits x 384 rows x 80B) = 122880
#define VTILE  61440
#define VSPLIT 30720
#define OFF_PH 141312      // 64 x 80B
#define OFF_PL 146432
#define OFF_L  151552      // 256 floats
#define SMEM_ATT 152576
#define OST 392            // epilogue stage stride (floats), reuses OFF_V area

typedef unsigned long long u64;

__device__ __align__(16) __nv_bfloat16 g_qh[B*NN*E];
__device__ __align__(16) __nv_bfloat16 g_ql[B*NN*E];
__device__ __align__(16) __nv_bfloat16 g_kh[B*NN*E];
__device__ __align__(16) __nv_bfloat16 g_kl[B*NN*E];
__device__ __align__(16) __nv_bfloat16 g_vth[TD*NNP];
__device__ __align__(16) __nv_bfloat16 g_vtl[TD*NNP];

// =================== helpers ===================
__device__ __forceinline__ uint32_t cvta_s(const void* p){
    return (uint32_t)__cvta_generic_to_shared(p);
}
__device__ __forceinline__ void cpa16(uint32_t d, const void* s){
    asm volatile("cp.async.cg.shared.global [%0],[%1],16;" :: "r"(d), "l"(s));
}
#define CP_COMMIT() asm volatile("cp.async.commit_group;")

__device__ __forceinline__ void mma16816(float* d, const uint32_t* a, const uint32_t* b){
    asm volatile("mma.sync.aligned.m16n8k16.row.col.f32.bf16.bf16.f32 "
        "{%0,%1,%2,%3},{%4,%5,%6,%7},{%8,%9},{%0,%1,%2,%3};"
        : "+f"(d[0]), "+f"(d[1]), "+f"(d[2]), "+f"(d[3])
        : "r"(a[0]), "r"(a[1]), "r"(a[2]), "r"(a[3]), "r"(b[0]), "r"(b[1]));
}

__device__ __forceinline__ float fexp(float x){   // valid |x| <= ~3
    float t = x * 1.4426950408889634f;
    float c = t + 12582912.f;
    int k = __float_as_int(c) - 0x4B400000;
    float f = t - (c - 12582912.f);
    float z = f * 0.6931471805599453f;
    float p = fmaf(z, 0.0083333333f, 0.0416666667f);
    p = fmaf(p, z, 0.1666666667f);
    p = fmaf(p, z, 0.5f);
    p = fmaf(p, z, 1.0f);
    p = fmaf(p, z, 1.0f);
    return __int_as_float(__float_as_int(p) + (k << 23));
}
__device__ __forceinline__ int imin(int a, int b){ return a < b ? a : b; }
__device__ __forceinline__ uint32_t pkbf(float a, float b){
    __nv_bfloat16 h0 = __float2bfloat16(a), h1 = __float2bfloat16(b);
    return (uint32_t)__bfloat16_as_ushort(h0) | ((uint32_t)__bfloat16_as_ushort(h1) << 16);
}
__device__ __forceinline__ u64 pk2(float a, float b){
    u64 r; asm("mov.b64 %0,{%1,%2};" : "=l"(r) : "f"(a), "f"(b)); return r;
}
__device__ __forceinline__ void ff2(u64 &d, u64 a, u64 b){
    asm("fma.rn.f32x2 %0,%1,%2,%0;" : "+l"(d) : "l"(a), "l"(b));
}
__device__ __forceinline__ float2 up2(u64 v){
    float2 r; asm("mov.b64 {%0,%1},%2;" : "=f"(r.x), "=f"(r.y) : "l"(v)); return r;
}

// ============================================================
// prep: V transposed [col][NNP kv] + bf16 hi/lo split
// ============================================================
__global__ __launch_bounds__(256) void prep_vt(const float* __restrict__ normal){
    int idx = blockIdx.x*256 + threadIdx.x;
    if (idx < TD*NNP){
        int n = idx >> 11, kv = idx & (NNP-1);
        float v = (kv < NN) ? normal[(size_t)kv*TD + n] : 0.f;
        __nv_bfloat16 h = __float2bfloat16(v);
        g_vth[idx] = h;
        g_vtl[idx] = __float2bfloat16(v - __bfloat162float(h));
    }
}

// ============================================================
// Kernel 1: q1/k1 = LN(xf@W + b) -> bf16 hi/lo splits
// ============================================================
#define K1_ROWS 64
#define W_CH 32
#define N_CH (TD / W_CH)
#define K1_XS 0
#define K1_WS 24576
#define K1_QK 32768
#define K1_MU 40960
#define K1_RS 41088
#define K1_SM_BYTES (41216*4)

__device__ __forceinline__ void k1_prefetch_w(float* ws, int tid, int c,
        const float* Wq, const float* Wk)
{
    if (c < N_CH) {
        float* dst = ws + (c & 1) * (W_CH * 128);
        int c0 = c * W_CH;
#pragma unroll
        for (int j = 0; j < 2; j++) {
            int idx = tid + j*512;
            int row = idx >> 5, c4 = idx & 31;
            const float* src = (c4 < 16)
                ? (Wq + (size_t)(c0 + row)*E + c4*4)
                : (Wk + (size_t)(c0 + row)*E + (c4 - 16)*4);
            cpa16(cvta_s(dst + row*128 + ((c4 < 16) ? c4*4 : 64 + (c4-16)*4)), src);
        }
    }
    CP_COMMIT();
}

__global__ __launch_bounds__(512, 1) void qk_ln_kernel(
    const float* __restrict__ x,
    const float* __restrict__ Wq, const float* __restrict__ bq,
    const float* __restrict__ Wk, const float* __restrict__ bk,
    const float* __restrict__ g0, const float* __restrict__ beta0,
    const float* __restrict__ g1, const float* __restrict__ beta1)
{
    extern __shared__ float sm1[];
    float* xs = sm1 + K1_XS;
    float* ws = sm1 + K1_WS;
    float* qk = sm1 + K1_QK;
    float* mu_sh = sm1 + K1_MU;
    float* rs_sh = sm1 + K1_RS;
    const int tid = threadIdx.x;
    const long base = (long)blockIdx.x * K1_ROWS;

    k1_prefetch_w(ws, tid, 0, Wq, Wk);
    k1_prefetch_w(ws, tid, 1, Wq, Wk);

    const float4* xp4 = (const float4*)(x + base*TD);
#pragma unroll
    for (int i = 0; i < 12; i++) ((float4*)xs)[tid + i*512] = xp4[tid + i*512];

    const int col = tid & 63;
    const int grp = tid >> 6;
    const int isK = grp >> 2;
    const int r0  = (grp & 3) * 16;
    const int wcol = isK*64 + col;

    u64 acc2[16];
#pragma unroll
    for (int r = 0; r < 16; r++) acc2[r] = 0ull;

    for (int c = 0; c < N_CH; c++) {
        const float* wb = ws + (c & 1) * (W_CH * 128);
        asm volatile("cp.async.wait_group 1;");
        __syncthreads();
#pragma unroll
        for (int i4l = 0; i4l < W_CH/4; i4l++) {
            int i4 = c*(W_CH/4) + i4l;
            u64 wa = pk2(wb[(i4l*4+0)*128+wcol], wb[(i4l*4+1)*128+wcol]);
            u64 wbp = pk2(wb[(i4l*4+2)*128+wcol], wb[(i4l*4+3)*128+wcol]);
#pragma unroll
            for (int r = 0; r < 16; r++) {
                ulonglong2 xv = ((const ulonglong2*)(xs + (r0 + r)*TD))[i4];
                ff2(acc2[r], xv.x, wa);
                ff2(acc2[r], xv.y, wbp);
            }
        }
        __syncthreads();
        k1_prefetch_w(ws, tid, c + 2, Wq, Wk);
    }

    const float bias = isK ? bk[col] : bq[col];
#pragma unroll
    for (int r = 0; r < 16; r++) {
        float2 f = up2(acc2[r]);
        qk[(r0 + r)*128 + isK*64 + col] = f.x + f.y + bias;
    }
    __syncthreads();

    if (tid < 128) {
        int r = tid & 63, h = tid >> 6;
        const float* v = qk + r*128 + h*64;
        float s = 0.f, s2 = 0.f;
#pragma unroll
        for (int j = 0; j < 64; j++) { float t = v[(j + r) & 63]; s += t; s2 += t*t; }
        float mu = s * (1.f/64.f);
        mu_sh[tid] = mu;
        rs_sh[tid] = rsqrtf(s2*(1.f/64.f) - mu*mu + 1e-5f);
    }
    __syncthreads();

    const float gg = isK ? g1[col] : g0[col];
    const float bb = isK ? beta1[col] : beta0[col];
    __nv_bfloat16* __restrict__ oh = isK ? g_kh : g_qh;
    __nv_bfloat16* __restrict__ ol = isK ? g_kl : g_ql;
#pragma unroll
    for (int r = 0; r < 16; r++) {
        float mu = mu_sh[isK*64 + r0 + r], rs = rs_sh[isK*64 + r0 + r];
        float val = (qk[(r0 + r)*128 + isK*64 + col] - mu) * rs * gg + bb;
        __nv_bfloat16 h = __float2bfloat16(val);
        size_t o = (size_t)(base + r0 + r)*E + col;
        oh[o] = h;
        ol[o] = __float2bfloat16(val - __bfloat162float(h));
    }
}

// ============================================================
// Kernel 2: warp-level bf16 mma.sync flash attention (hi/lo split)
// 512 threads = 16 warps: rg = wid>>2 (16 rows), cq = wid&3
//   S:  warp -> rows rg*16..+15, kv cols cq*8..+7 (1 n-tile)
//   PV: warp -> rows rg*16..+15, out cols cq*96..+95 (12 n-tiles)
// ============================================================
__device__ __forceinline__ void att_prefetch(char* smem, int tid, int t, int b){
    if (t < NTK){
        int st = t & 1;
        {                                        // K: 512 chunks, one per thread
            int c = tid;
            int split = c >> 8, rem = c & 255;
            int kv = rem >> 3, ch = rem & 7;
            int g = imin(t*BC + kv, NN-1);
            const __nv_bfloat16* src = (split ? g_kl : g_kh) + ((size_t)b*NN + g)*E + ch*8;
            cpa16(cvta_s(smem + OFF_K + st*KTILE + split*KSPLIT + kv*144 + ch*16), src);
        }
#pragma unroll
        for (int j = 0; j < 6; j++){             // V: 3072 chunks
            int c = tid + j*512;
            int split = (c >= 1536) ? 1 : 0;
            int rem = c - split*1536;
            int col = rem >> 2, ch = rem & 3;
            const __nv_bfloat16* src = (split ? g_vtl : g_vth) + (size_t)col*NNP + t*BC + ch*8;
            cpa16(cvta_s(smem + OFF_V + st*VTILE + split*VSPLIT + col*80 + ch*16), src);
        }
    }
    CP_COMMIT();
}

__global__ __launch_bounds__(512, 1) void attn_mma(
    const float* __restrict__ x,
    const float* __restrict__ Win,
    float* __restrict__ out)
{
    extern __shared__ char smem[];
    const int tid = threadIdx.x;
    const int wid = tid >> 5, lane = tid & 31;
    const int gid = lane >> 2, tig = lane & 3;
    const int rg = wid >> 2, cq = wid & 3;
    const int b = blockIdx.y;
    const int n0 = blockIdx.x * BR;
    const int r0 = rg * 16;
    const float scale = 0.022360679774997897f;   // 1/sqrt(2000)

    // ---- Q fragments hoisted into registers for the whole kernel
    uint32_t aqh[4][4], aql[4][4];
    {
        int nA = imin(n0 + r0 + gid, NN-1);
        int nB = imin(n0 + r0 + gid + 8, NN-1);
        const uint32_t* qh = (const uint32_t*)(g_qh + (size_t)b*NN*E);
        const uint32_t* ql = (const uint32_t*)(g_ql + (size_t)b*NN*E);
#pragma unroll
        for (int ks = 0; ks < 4; ks++){
            int c0 = ks*8 + tig;
            aqh[ks][0] = qh[nA*32 + c0];     aqh[ks][1] = qh[nB*32 + c0];
            aqh[ks][2] = qh[nA*32 + c0 + 4]; aqh[ks][3] = qh[nB*32 + c0 + 4];
            aql[ks][0] = ql[nA*32 + c0];     aql[ks][1] = ql[nB*32 + c0];
            aql[ks][2] = ql[nA*32 + c0 + 4]; aql[ks][3] = ql[nB*32 + c0 + 4];
        }
    }

    att_prefetch(smem, tid, 0, b);
    att_prefetch(smem, tid, 1, b);

    float dacc[12][4];
#pragma unroll
    for (int nt = 0; nt < 12; nt++)
#pragma unroll
        for (int c = 0; c < 4; c++) dacc[nt][c] = 0.f;
    float lA = 0.f, lB = 0.f;

    uint32_t* ph = (uint32_t*)(smem + OFF_PH);
    uint32_t* pl = (uint32_t*)(smem + OFF_PL);

    for (int t = 0; t < NTK; t++){
        const int st = t & 1;
        asm volatile("cp.async.wait_group 1;");
        __syncthreads();

        // ---- S = Qh*Kh + Qh*Kl + Ql*Kh (per warp: 1 n-tile of 8 kv)
        float sacc[4] = {0.f, 0.f, 0.f, 0.f};
        {
            const uint32_t* kh = (const uint32_t*)(smem + OFF_K + st*KTILE);
            const uint32_t* kl = (const uint32_t*)(smem + OFF_K + st*KTILE + KSPLIT);
            int base = (cq*8 + gid) * 36;
#pragma unroll
            for (int ks = 0; ks < 4; ks++){
                uint32_t bh[2] = { kh[base + ks*8 + tig], kh[base + ks*8 + tig + 4] };
                uint32_t bl[2] = { kl[base + ks*8 + tig], kl[base + ks*8 + tig + 4] };
                mma16816(sacc, aqh[ks], bh);
                mma16816(sacc, aqh[ks], bl);
                mma16816(sacc, aql[ks], bh);
            }
        }

        // ---- exp + split + store P hi/lo
        {
            int colg = t*BC + cq*8 + tig*2;
            bool m0 = colg < NN, m1 = (colg + 1) < NN;
            float p0 = m0 ? fexp(sacc[0]*scale) : 0.f;
            float p1 = m1 ? fexp(sacc[1]*scale) : 0.f;
            float p2 = m0 ? fexp(sacc[2]*scale) : 0.f;
            float p3 = m1 ? fexp(sacc[3]*scale) : 0.f;
            lA += p0 + p1; lB += p2 + p3;
            float h0 = __bfloat162float(__float2bfloat16(p0));
            float h1 = __bfloat162float(__float2bfloat16(p1));
            float h2 = __bfloat162float(__float2bfloat16(p2));
            float h3 = __bfloat162float(__float2bfloat16(p3));
            int wa = (r0 + gid)*20 + cq*4 + tig;
            int wb = (r0 + gid + 8)*20 + cq*4 + tig;
            ph[wa] = pkbf(h0, h1);
            ph[wb] = pkbf(h2, h3);
            pl[wa] = pkbf(p0 - h0, p1 - h1);
            pl[wb] = pkbf(p2 - h2, p3 - h3);
        }
        __syncthreads();

        // ---- PV: dacc += Ph*Vh + Ph*Vl + Pl*Vh (12 n-tiles x 2 k-steps)
        {
            const uint32_t* vh = (const uint32_t*)(smem + OFF_V + st*VTILE);
            const uint32_t* vl = (const uint32_t*)(smem + OFF_V + st*VTILE + VSPLIT);
#pragma unroll
            for (int ks = 0; ks < 2; ks++){
                int ra = (r0 + gid)*20 + ks*8 + tig;
                int rb = (r0 + gid + 8)*20 + ks*8 + tig;
                uint32_t pah[4] = { ph[ra], ph[rb], ph[ra+4], ph[rb+4] };
                uint32_t pal[4] = { pl[ra], pl[rb], pl[ra+4], pl[rb+4] };
#pragma unroll
                for (int nt = 0; nt < 12; nt++){
                    int vb = (cq*96 + nt*8 + gid)*20 + ks*8 + tig;
                    uint32_t bh[2] = { vh[vb], vh[vb+4] };
                    uint32_t bl[2] = { vl[vb], vl[vb+4] };
                    mma16816(dacc[nt], pah, bh);
                    mma16816(dacc[nt], pah, bl);
                    mma16816(dacc[nt], pal, bh);
                }
            }
        }
        __syncthreads();
        att_prefetch(smem, tid, t + 2, b);
    }

    // ---- l reduction: 4 partials per row (one per cq)
    lA += __shfl_xor_sync(0xffffffffu, lA, 1);
    lA += __shfl_xor_sync(0xffffffffu, lA, 2);
    lB += __shfl_xor_sync(0xffffffffu, lB, 1);
    lB += __shfl_xor_sync(0xffffffffu, lB, 2);
    float* l_s = (float*)(smem + OFF_L);
    if (tig == 0){
        l_s[cq*64 + r0 + gid]     = lA;
        l_s[cq*64 + r0 + gid + 8] = lB;
    }
    __syncthreads();
    float invA = 1.f / (l_s[r0 + gid]      + l_s[64 + r0 + gid]
                      + l_s[128 + r0 + gid] + l_s[192 + r0 + gid]);
    float invB = 1.f / (l_s[r0 + gid + 8]      + l_s[64 + r0 + gid + 8]
                      + l_s[128 + r0 + gid + 8] + l_s[192 + r0 + gid + 8]);

    // ---- stage data = dacc / l into OFF_V area (stride OST)
    float* stage = (float*)(smem + OFF_V);
#pragma unroll
    for (int nt = 0; nt < 12; nt++){
        int col = cq*96 + nt*8 + tig*2;
        float* sa = stage + (r0 + gid)*OST + col;
        sa[0] = dacc[nt][0]*invA; sa[1] = dacc[nt][1]*invA;
        float* sb = stage + (r0 + gid + 8)*OST + col;
        sb[0] = dacc[nt][2]*invB; sb[1] = dacc[nt][3]*invB;
    }
    __syncthreads();

    // ---- RPPsAtt weights per row
    float* w_s = (float*)(smem + OFF_PH);   // 64*24 floats
    if (tid < BR){
        int n = n0 + tid;
        if (n < NN){
            const float* xl = x + ((size_t)b*NN + n)*TD + (TT - 1)*DD;
            float q16[DD];
#pragma unroll
            for (int dp = 0; dp < DD; dp++){
                float s = 0.f;
#pragma unroll
                for (int d = 0; d < DD; d++) s = fmaf(xl[d], Win[d*DD + dp], s);
                q16[dp] = s;
            }
            const float* row = stage + tid*OST;
            float att[TT]; float mx = -1e30f;
#pragma unroll
            for (int t2 = 0; t2 < TT; t2++){
                float s = 0.f;
#pragma unroll
                for (int d = 0; d < DD; d++) s = fmaf(q16[d], row[t2*DD + d], s);
                att[t2] = s; mx = fmaxf(mx, s);
            }
            float se = 0.f;
#pragma unroll
            for (int t2 = 0; t2 < TT; t2++){ float e = __expf(att[t2] - mx); att[t2] = e; se += e; }
            float si = 1.f / se;
#pragma unroll
            for (int t2 = 0; t2 < TT; t2++) w_s[tid*TT + t2] = att[t2] * si;
        }
    }
    __syncthreads();

    // ---- out = data + weight[..., None]
    int nrows = NN - n0; if (nrows > BR) nrows = BR;
    float4* outp = (float4*)(out + ((size_t)b*NN + n0)*TD);
    for (int i = tid; i < nrows*96; i += 512){
        int r = i / 96, c4 = i - r*96;
        const float* sr = stage + r*OST + c4*4;
        float w = w_s[r*TT + (c4 >> 2)];
        float4 v;
        v.x = sr[0] + w; v.y = sr[1] + w; v.z = sr[2] + w; v.w = sr[3] + w;
        outp[i] = v;
    }
}

// ============================================================
extern "C" void kernel_launch(void* const* d_in, const int* in_sizes, int n_in,
                              void* d_out, int out_size)
{
    (void)in_sizes; (void)n_in; (void)out_size;
    const float* x     = (const float*)d_in[0];
    const float* Wq    = (const float*)d_in[1];
    const float* bq    = (const float*)d_in[2];
    const float* Wk    = (const float*)d_in[3];
    const float* bk    = (const float*)d_in[4];
    const float* g0    = (const float*)d_in[5];
    const float* beta0 = (const float*)d_in[6];
    const float* g1    = (const float*)d_in[7];
    const float* beta1 = (const float*)d_in[8];
    const float* nrm   = (const float*)d_in[9];
    const float* Win   = (const float*)d_in[10];
    float* out = (float*)d_out;

    cudaFuncSetAttribute(qk_ln_kernel, cudaFuncAttributeMaxDynamicSharedMemorySize, K1_SM_BYTES);
    cudaFuncSetAttribute(attn_mma,     cudaFuncAttributeMaxDynamicSharedMemorySize, SMEM_ATT);

    prep_vt<<<(TD*NNP + 255)/256, 256>>>(nrm);
    qk_ln_kernel<<<(B*NN)/K1_ROWS, 512, K1_SM_BYTES>>>(x, Wq, bq, Wk, bk, g0, beta0, g1, beta1);

    dim3 grid((NN + BR - 1)/BR, B);
    attn_mma<<<grid, 512, SMEM_ATT>>>(x, Win, out);
}

// round 10
// speedup vs baseline: 1.0981x; 1.0170x over previous
#include <cuda_runtime.h>
#include <cuda_bf16.h>
#include <cstdint>

#define B    32
#define NN   2000
#define TD   384
#define E    64
#define TT   24
#define DD   16
#define NNP  2048

#define BR   128
#define BC   32
#define NTK  63

// ---- attn smem byte layout
#define OFF_Q   0            // 2 splits x 128 rows x 144B = 36864
#define QSPLIT  18432
#define OFF_K   36864        // 2 stages x (2 splits x 32 x 144B) = 18432
#define KTILE   9216
#define KSPLIT  4608
#define OFF_V   55296        // 2 stages x (2 splits x 384 x 80B) = 122880
#define VTILE   61440
#define VSPLIT  30720
#define OFF_P   178176       // 2 splits x 128 rows x 80B = 20480
#define PSPLIT  10240
#define SMEM_ATT 198656

typedef unsigned long long u64;

__device__ __align__(16) __nv_bfloat16 g_qh[B*NN*E];
__device__ __align__(16) __nv_bfloat16 g_ql[B*NN*E];
__device__ __align__(16) __nv_bfloat16 g_kh[B*NN*E];
__device__ __align__(16) __nv_bfloat16 g_kl[B*NN*E];
__device__ __align__(16) __nv_bfloat16 g_vth[TD*NNP];
__device__ __align__(16) __nv_bfloat16 g_vtl[TD*NNP];

// =================== helpers ===================
__device__ __forceinline__ uint32_t cvta_s(const void* p){
    return (uint32_t)__cvta_generic_to_shared(p);
}
__device__ __forceinline__ void cpa16(uint32_t d, const void* s){
    asm volatile("cp.async.cg.shared.global [%0],[%1],16;" :: "r"(d), "l"(s));
}
#define CP_COMMIT() asm volatile("cp.async.commit_group;")

__device__ __forceinline__ void mma16816(float* d, const uint32_t* a, const uint32_t* b){
    asm volatile("mma.sync.aligned.m16n8k16.row.col.f32.bf16.bf16.f32 "
        "{%0,%1,%2,%3},{%4,%5,%6,%7},{%8,%9},{%0,%1,%2,%3};"
        : "+f"(d[0]), "+f"(d[1]), "+f"(d[2]), "+f"(d[3])
        : "r"(a[0]), "r"(a[1]), "r"(a[2]), "r"(a[3]), "r"(b[0]), "r"(b[1]));
}

__device__ __forceinline__ float fexp(float x){   // valid |x| <= ~3
    float t = x * 1.4426950408889634f;
    float c = t + 12582912.f;
    int k = __float_as_int(c) - 0x4B400000;
    float f = t - (c - 12582912.f);
    float z = f * 0.6931471805599453f;
    float p = fmaf(z, 0.0083333333f, 0.0416666667f);
    p = fmaf(p, z, 0.1666666667f);
    p = fmaf(p, z, 0.5f);
    p = fmaf(p, z, 1.0f);
    p = fmaf(p, z, 1.0f);
    return __int_as_float(__float_as_int(p) + (k << 23));
}
__device__ __forceinline__ int imin(int a, int b){ return a < b ? a : b; }
__device__ __forceinline__ uint32_t pkbf(float a, float b){
    __nv_bfloat16 h0 = __float2bfloat16(a), h1 = __float2bfloat16(b);
    return (uint32_t)__bfloat16_as_ushort(h0) | ((uint32_t)__bfloat16_as_ushort(h1) << 16);
}
__device__ __forceinline__ u64 pk2(float a, float b){
    u64 r; asm("mov.b64 %0,{%1,%2};" : "=l"(r) : "f"(a), "f"(b)); return r;
}
__device__ __forceinline__ void ff2(u64 &d, u64 a, u64 b){
    asm("fma.rn.f32x2 %0,%1,%2,%0;" : "+l"(d) : "l"(a), "l"(b));
}
__device__ __forceinline__ float2 up2(u64 v){
    float2 r; asm("mov.b64 {%0,%1},%2;" : "=f"(r.x), "=f"(r.y) : "l"(v)); return r;
}

// ============================================================
// prep: V transposed [col][NNP kv] + bf16 hi/lo split
// ============================================================
__global__ __launch_bounds__(256) void prep_vt(const float* __restrict__ normal){
    int idx = blockIdx.x*256 + threadIdx.x;
    if (idx < TD*NNP){
        int n = idx >> 11, kv = idx & (NNP-1);
        float v = (kv < NN) ? normal[(size_t)kv*TD + n] : 0.f;
        __nv_bfloat16 h = __float2bfloat16(v);
        g_vth[idx] = h;
        g_vtl[idx] = __float2bfloat16(v - __bfloat162float(h));
    }
}

// ============================================================
// Kernel 1: q1/k1 = LN(xf@W + b) -> bf16 hi/lo splits
// ============================================================
#define K1_ROWS 64
#define W_CH 32
#define N_CH (TD / W_CH)
#define K1_XS 0
#define K1_WS 24576
#define K1_QK 32768
#define K1_MU 40960
#define K1_RS 41088
#define K1_SM_BYTES (41216*4)

__device__ __forceinline__ void k1_prefetch_w(float* ws, int tid, int c,
        const float* Wq, const float* Wk)
{
    if (c < N_CH) {
        float* dst = ws + (c & 1) * (W_CH * 128);
        int c0 = c * W_CH;
#pragma unroll
        for (int j = 0; j < 2; j++) {
            int idx = tid + j*512;
            int row = idx >> 5, c4 = idx & 31;
            const float* src = (c4 < 16)
                ? (Wq + (size_t)(c0 + row)*E + c4*4)
                : (Wk + (size_t)(c0 + row)*E + (c4 - 16)*4);
            cpa16(cvta_s(dst + row*128 + ((c4 < 16) ? c4*4 : 64 + (c4-16)*4)), src);
        }
    }
    CP_COMMIT();
}

__global__ __launch_bounds__(512, 1) void qk_ln_kernel(
    const float* __restrict__ x,
    const float* __restrict__ Wq, const float* __restrict__ bq,
    const float* __restrict__ Wk, const float* __restrict__ bk,
    const float* __restrict__ g0, const float* __restrict__ beta0,
    const float* __restrict__ g1, const float* __restrict__ beta1)
{
    extern __shared__ float sm1[];
    float* xs = sm1 + K1_XS;
    float* ws = sm1 + K1_WS;
    float* qk = sm1 + K1_QK;
    float* mu_sh = sm1 + K1_MU;
    float* rs_sh = sm1 + K1_RS;
    const int tid = threadIdx.x;
    const long base = (long)blockIdx.x * K1_ROWS;

    k1_prefetch_w(ws, tid, 0, Wq, Wk);
    k1_prefetch_w(ws, tid, 1, Wq, Wk);

    const float4* xp4 = (const float4*)(x + base*TD);
#pragma unroll
    for (int i = 0; i < 12; i++) ((float4*)xs)[tid + i*512] = xp4[tid + i*512];

    const int col = tid & 63;
    const int grp = tid >> 6;
    const int isK = grp >> 2;
    const int r0  = (grp & 3) * 16;
    const int wcol = isK*64 + col;

    u64 acc2[16];
#pragma unroll
    for (int r = 0; r < 16; r++) acc2[r] = 0ull;

    for (int c = 0; c < N_CH; c++) {
        const float* wb = ws + (c & 1) * (W_CH * 128);
        asm volatile("cp.async.wait_group 1;");
        __syncthreads();
#pragma unroll
        for (int i4l = 0; i4l < W_CH/4; i4l++) {
            int i4 = c*(W_CH/4) + i4l;
            u64 wa = pk2(wb[(i4l*4+0)*128+wcol], wb[(i4l*4+1)*128+wcol]);
            u64 wbp = pk2(wb[(i4l*4+2)*128+wcol], wb[(i4l*4+3)*128+wcol]);
#pragma unroll
            for (int r = 0; r < 16; r++) {
                ulonglong2 xv = ((const ulonglong2*)(xs + (r0 + r)*TD))[i4];
                ff2(acc2[r], xv.x, wa);
                ff2(acc2[r], xv.y, wbp);
            }
        }
        __syncthreads();
        k1_prefetch_w(ws, tid, c + 2, Wq, Wk);
    }

    const float bias = isK ? bk[col] : bq[col];
#pragma unroll
    for (int r = 0; r < 16; r++) {
        float2 f = up2(acc2[r]);
        qk[(r0 + r)*128 + isK*64 + col] = f.x + f.y + bias;
    }
    __syncthreads();

    if (tid < 128) {
        int r = tid & 63, h = tid >> 6;
        const float* v = qk + r*128 + h*64;
        float s = 0.f, s2 = 0.f;
#pragma unroll
        for (int j = 0; j < 64; j++) { float t = v[(j + r) & 63]; s += t; s2 += t*t; }
        float mu = s * (1.f/64.f);
        mu_sh[tid] = mu;
        rs_sh[tid] = rsqrtf(s2*(1.f/64.f) - mu*mu + 1e-5f);
    }
    __syncthreads();

    const float gg = isK ? g1[col] : g0[col];
    const float bb = isK ? beta1[col] : beta0[col];
    __nv_bfloat16* __restrict__ oh = isK ? g_kh : g_qh;
    __nv_bfloat16* __restrict__ ol = isK ? g_kl : g_ql;
#pragma unroll
    for (int r = 0; r < 16; r++) {
        float mu = mu_sh[isK*64 + r0 + r], rs = rs_sh[isK*64 + r0 + r];
        float val = (qk[(r0 + r)*128 + isK*64 + col] - mu) * rs * gg + bb;
        __nv_bfloat16 h = __float2bfloat16(val);
        size_t o = (size_t)(base + r0 + r)*E + col;
        oh[o] = h;
        ol[o] = __float2bfloat16(val - __bfloat162float(h));
    }
}

// ============================================================
// Kernel 2: warp-level bf16 mma.sync flash attention (hi/lo split)
// BR=128 rows/CTA, 256 threads = 8 warps.
// Warp w: rows w*16..+15; S over all 32 kv (nt 0..3); PV over all
// 384 cols (nt 0..47). Epilogue fully in registers (no smem stage).
// ============================================================
__device__ __forceinline__ void att_prefetch(char* smem, int tid, int t, int b){
    if (t < NTK){
        int st = t & 1;
#pragma unroll
        for (int j = 0; j < 2; j++){            // K: 512 chunks
            int c = tid + j*256;
            int split = c >> 8, rem = c & 255;
            int kv = rem >> 3, ch = rem & 7;
            int g = imin(t*BC + kv, NN-1);
            const __nv_bfloat16* src = (split ? g_kl : g_kh) + ((size_t)b*NN + g)*E + ch*8;
            cpa16(cvta_s(smem + OFF_K + st*KTILE + split*KSPLIT + kv*144 + ch*16), src);
        }
#pragma unroll
        for (int j = 0; j < 12; j++){           // V: 3072 chunks
            int c = tid + j*256;
            int split = (c >= 1536) ? 1 : 0;
            int rem = c - split*1536;
            int col = rem >> 2, ch = rem & 3;
            const __nv_bfloat16* src = (split ? g_vtl : g_vth) + (size_t)col*NNP + t*BC + ch*8;
            cpa16(cvta_s(smem + OFF_V + st*VTILE + split*VSPLIT + col*80 + ch*16), src);
        }
    }
    CP_COMMIT();
}

__global__ __launch_bounds__(256, 1) void attn_mma(
    const float* __restrict__ x,
    const float* __restrict__ Win,
    float* __restrict__ out)
{
    extern __shared__ char smem[];
    const int tid = threadIdx.x;
    const int wid = tid >> 5, lane = tid & 31;
    const int gid = lane >> 2, tig = lane & 3;
    const int b = blockIdx.y;
    const int n0 = blockIdx.x * BR;
    const int r0 = wid * 16;
    const float scale = 0.022360679774997897f;   // 1/sqrt(2000)

    // ---- prologue: Q tile (both splits) into smem via cp.async
#pragma unroll
    for (int j = 0; j < 8; j++){
        int c = tid + j*256;                    // 0..2047
        int split = c >> 10, rem = c & 1023;
        int row = rem >> 3, ch = rem & 7;
        int g = imin(n0 + row, NN-1);
        const __nv_bfloat16* src = (split ? g_ql : g_qh) + ((size_t)b*NN + g)*E + ch*8;
        cpa16(cvta_s(smem + OFF_Q + split*QSPLIT + row*144 + ch*16), src);
    }
    att_prefetch(smem, tid, 0, b);   // commits {Q + tile0}
    att_prefetch(smem, tid, 1, b);

    float dacc[48][4];
#pragma unroll
    for (int nt = 0; nt < 48; nt++)
#pragma unroll
        for (int c = 0; c < 4; c++) dacc[nt][c] = 0.f;
    float lA = 0.f, lB = 0.f;

    const uint32_t* qh_s = (const uint32_t*)(smem + OFF_Q);
    const uint32_t* ql_s = (const uint32_t*)(smem + OFF_Q + QSPLIT);
    uint32_t* php = (uint32_t*)(smem + OFF_P);
    uint32_t* plp = (uint32_t*)(smem + OFF_P + PSPLIT);

    for (int t = 0; t < NTK; t++){
        const int st = t & 1;
        asm volatile("cp.async.wait_group 1;");
        __syncthreads();

        // ---- S = Qh*Kh + Qh*Kl + Ql*Kh (warp: 16 rows x 32 kv)
        float sacc[4][4];
#pragma unroll
        for (int nt = 0; nt < 4; nt++)
#pragma unroll
            for (int c = 0; c < 4; c++) sacc[nt][c] = 0.f;
        {
            const uint32_t* kh = (const uint32_t*)(smem + OFF_K + st*KTILE);
            const uint32_t* kl = (const uint32_t*)(smem + OFF_K + st*KTILE + KSPLIT);
#pragma unroll
            for (int ks = 0; ks < 4; ks++){
                int qa = (r0 + gid)*36 + ks*8 + tig;
                int qb = qa + 8*36;
                uint32_t ah[4] = { qh_s[qa], qh_s[qb], qh_s[qa+4], qh_s[qb+4] };
                uint32_t al[4] = { ql_s[qa], ql_s[qb], ql_s[qa+4], ql_s[qb+4] };
#pragma unroll
                for (int nt = 0; nt < 4; nt++){
                    int kb = (nt*8 + gid)*36 + ks*8 + tig;
                    uint32_t bh[2] = { kh[kb], kh[kb+4] };
                    uint32_t bl[2] = { kl[kb], kl[kb+4] };
                    mma16816(sacc[nt], ah, bh);
                    mma16816(sacc[nt], ah, bl);
                    mma16816(sacc[nt], al, bh);
                }
            }
        }

        // ---- exp + split + store P hi/lo
#pragma unroll
        for (int nt = 0; nt < 4; nt++){
            int colg = t*BC + nt*8 + tig*2;
            bool m0 = colg < NN, m1 = (colg + 1) < NN;
            float p0 = m0 ? fexp(sacc[nt][0]*scale) : 0.f;
            float p1 = m1 ? fexp(sacc[nt][1]*scale) : 0.f;
            float p2 = m0 ? fexp(sacc[nt][2]*scale) : 0.f;
            float p3 = m1 ? fexp(sacc[nt][3]*scale) : 0.f;
            lA += p0 + p1; lB += p2 + p3;
            float h0 = __bfloat162float(__float2bfloat16(p0));
            float h1 = __bfloat162float(__float2bfloat16(p1));
            float h2 = __bfloat162float(__float2bfloat16(p2));
            float h3 = __bfloat162float(__float2bfloat16(p3));
            int wa = (r0 + gid)*20 + nt*4 + tig;
            int wb = wa + 8*20;
            php[wa] = pkbf(h0, h1);
            php[wb] = pkbf(h2, h3);
            plp[wa] = pkbf(p0 - h0, p1 - h1);
            plp[wb] = pkbf(p2 - h2, p3 - h3);
        }
        __syncthreads();

        // ---- PV: dacc += Ph*Vh + Ph*Vl + Pl*Vh (48 n-tiles x 2 k-steps)
        {
            const uint32_t* vh = (const uint32_t*)(smem + OFF_V + st*VTILE);
            const uint32_t* vl = (const uint32_t*)(smem + OFF_V + st*VTILE + VSPLIT);
#pragma unroll
            for (int ks = 0; ks < 2; ks++){
                int ra = (r0 + gid)*20 + ks*8 + tig;
                int rb = ra + 8*20;
                uint32_t pah[4] = { php[ra], php[rb], php[ra+4], php[rb+4] };
                uint32_t pal[4] = { plp[ra], plp[rb], plp[ra+4], plp[rb+4] };
#pragma unroll
                for (int nt = 0; nt < 48; nt++){
                    int vb = (nt*8 + gid)*20 + ks*8 + tig;
                    uint32_t bh[2] = { vh[vb], vh[vb+4] };
                    uint32_t bl[2] = { vl[vb], vl[vb+4] };
                    mma16816(dacc[nt], pah, bh);
                    mma16816(dacc[nt], pah, bl);
                    mma16816(dacc[nt], pal, bh);
                }
            }
        }
        __syncthreads();
        att_prefetch(smem, tid, t + 2, b);
    }

    // ---- l: full rows live in this warp; reduce over the quad (tig)
    lA += __shfl_xor_sync(0xffffffffu, lA, 1);
    lA += __shfl_xor_sync(0xffffffffu, lA, 2);
    lB += __shfl_xor_sync(0xffffffffu, lB, 1);
    lB += __shfl_xor_sync(0xffffffffu, lB, 2);
    const float invA = 1.f / lA;
    const float invB = 1.f / lB;

    // ---- q16 = x[b, n, 23, :] @ Win for my two rows
    const int nA = imin(n0 + r0 + gid, NN-1);
    const int nB = imin(n0 + r0 + gid + 8, NN-1);
    float q16A[DD], q16B[DD];
    {
        const float* xa = x + ((size_t)b*NN + nA)*TD + (TT-1)*DD;
        const float* xb = x + ((size_t)b*NN + nB)*TD + (TT-1)*DD;
#pragma unroll
        for (int dp = 0; dp < DD; dp++){
            float sa = 0.f, sb = 0.f;
#pragma unroll
            for (int d = 0; d < DD; d++){
                float w = Win[d*DD + dp];
                sa = fmaf(xa[d], w, sa);
                sb = fmaf(xb[d], w, sb);
            }
            q16A[dp] = sa; q16B[dp] = sb;
        }
    }

    // ---- att scores per t2 (each lane: 4 of the 16 d-cols; quad-reduce)
    float wAr[TT], wBr[TT];
#pragma unroll
    for (int t2 = 0; t2 < TT; t2++){
        int nt0 = 2*t2, nt1 = nt0 + 1;
        float aA = q16A[tig*2]   * dacc[nt0][0] + q16A[tig*2+1]   * dacc[nt0][1]
                 + q16A[8+tig*2] * dacc[nt1][0] + q16A[9+tig*2]   * dacc[nt1][1];
        float aB = q16B[tig*2]   * dacc[nt0][2] + q16B[tig*2+1]   * dacc[nt0][3]
                 + q16B[8+tig*2] * dacc[nt1][2] + q16B[9+tig*2]   * dacc[nt1][3];
        aA += __shfl_xor_sync(0xffffffffu, aA, 1);
        aA += __shfl_xor_sync(0xffffffffu, aA, 2);
        aB += __shfl_xor_sync(0xffffffffu, aB, 1);
        aB += __shfl_xor_sync(0xffffffffu, aB, 2);
        wAr[t2] = aA * invA;
        wBr[t2] = aB * invB;
    }
    // softmax over 24
    {
        float mA = -1e30f, mB = -1e30f;
#pragma unroll
        for (int t2 = 0; t2 < TT; t2++){ mA = fmaxf(mA, wAr[t2]); mB = fmaxf(mB, wBr[t2]); }
        float sA = 0.f, sB = 0.f;
#pragma unroll
        for (int t2 = 0; t2 < TT; t2++){
            float eA = __expf(wAr[t2] - mA); wAr[t2] = eA; sA += eA;
            float eB = __expf(wBr[t2] - mB); wBr[t2] = eB; sB += eB;
        }
        float iA = 1.f / sA, iB = 1.f / sB;
#pragma unroll
        for (int t2 = 0; t2 < TT; t2++){ wAr[t2] *= iA; wBr[t2] *= iB; }
    }

    // ---- out = data/l + weight  (2 floats per thread per nt; 32B sectors)
    const bool vA = (n0 + r0 + gid) < NN;
    const bool vB = (n0 + r0 + gid + 8) < NN;
    float* orowA = out + ((size_t)b*NN + nA)*TD;
    float* orowB = out + ((size_t)b*NN + nB)*TD;
#pragma unroll
    for (int nt = 0; nt < 48; nt++){
        int col = nt*8 + tig*2;
        int t2 = nt >> 1;
        if (vA){
            float2 v; v.x = fmaf(dacc[nt][0], invA, wAr[t2]);
            v.y = fmaf(dacc[nt][1], invA, wAr[t2]);
            *(float2*)(orowA + col) = v;
        }
        if (vB){
            float2 v; v.x = fmaf(dacc[nt][2], invB, wBr[t2]);
            v.y = fmaf(dacc[nt][3], invB, wBr[t2]);
            *(float2*)(orowB + col) = v;
        }
    }
}

// ============================================================
extern "C" void kernel_launch(void* const* d_in, const int* in_sizes, int n_in,
                              void* d_out, int out_size)
{
    (void)in_sizes; (void)n_in; (void)out_size;
    const float* x     = (const float*)d_in[0];
    const float* Wq    = (const float*)d_in[1];
    const float* bq    = (const float*)d_in[2];
    const float* Wk    = (const float*)d_in[3];
    const float* bk    = (const float*)d_in[4];
    const float* g0    = (const float*)d_in[5];
    const float* beta0 = (const float*)d_in[6];
    const float* g1    = (const float*)d_in[7];
    const float* beta1 = (const float*)d_in[8];
    const float* nrm   = (const float*)d_in[9];
    const float* Win   = (const float*)d_in[10];
    float* out = (float*)d_out;

    cudaFuncSetAttribute(qk_ln_kernel, cudaFuncAttributeMaxDynamicSharedMemorySize, K1_SM_BYTES);
    cudaFuncSetAttribute(attn_mma,     cudaFuncAttributeMaxDynamicSharedMemorySize, SMEM_ATT);

    prep_vt<<<(TD*NNP + 255)/256, 256>>>(nrm);
    qk_ln_kernel<<<(B*NN)/K1_ROWS, 512, K1_SM_BYTES>>>(x, Wq, bq, Wk, bk, g0, beta0, g1, beta1);

    dim3 grid((NN + BR - 1)/BR, B);
    attn_mma<<<grid, 256, SMEM_ATT>>>(x, Win, out);
}

// round 11
// speedup vs baseline: 2.0078x; 1.8284x over previous
#include <cuda_runtime.h>
#include <cuda_fp16.h>
#include <cstdint>

#define B    32
#define NN   2000
#define TD   384
#define E    64
#define TT   24
#define DD   16
#define NNP  2048

#define BR   128
#define BC   32
#define NTK  63

// ---- attn smem byte layout (fp16, single term)
#define OFF_Q   0            // 128 rows x 144B = 18432
#define OFF_K   18432        // 2 stages x 32 x 144B = 9216
#define KTILE   4608
#define OFF_V   27648        // 2 stages x 384 x 80B = 61440
#define VTILE   30720
#define OFF_P   89088        // 128 rows x 80B = 10240
#define SMEM_ATT 99328

typedef unsigned long long u64;

__device__ __align__(16) __half g_qf[B*NN*E];
__device__ __align__(16) __half g_kf[B*NN*E];
__device__ __align__(16) __half g_vtf[TD*NNP];

// =================== helpers ===================
__device__ __forceinline__ uint32_t cvta_s(const void* p){
    return (uint32_t)__cvta_generic_to_shared(p);
}
__device__ __forceinline__ void cpa16(uint32_t d, const void* s){
    asm volatile("cp.async.cg.shared.global [%0],[%1],16;" :: "r"(d), "l"(s));
}
#define CP_COMMIT() asm volatile("cp.async.commit_group;")

__device__ __forceinline__ void mma16816h(float* d, const uint32_t* a, const uint32_t* b){
    asm volatile("mma.sync.aligned.m16n8k16.row.col.f32.f16.f16.f32 "
        "{%0,%1,%2,%3},{%4,%5,%6,%7},{%8,%9},{%0,%1,%2,%3};"
        : "+f"(d[0]), "+f"(d[1]), "+f"(d[2]), "+f"(d[3])
        : "r"(a[0]), "r"(a[1]), "r"(a[2]), "r"(a[3]), "r"(b[0]), "r"(b[1]));
}

__device__ __forceinline__ float fexp(float x){   // valid |x| <= ~3
    float t = x * 1.4426950408889634f;
    float c = t + 12582912.f;
    int k = __float_as_int(c) - 0x4B400000;
    float f = t - (c - 12582912.f);
    float z = f * 0.6931471805599453f;
    float p = fmaf(z, 0.0083333333f, 0.0416666667f);
    p = fmaf(p, z, 0.1666666667f);
    p = fmaf(p, z, 0.5f);
    p = fmaf(p, z, 1.0f);
    p = fmaf(p, z, 1.0f);
    return __int_as_float(__float_as_int(p) + (k << 23));
}
__device__ __forceinline__ int imin(int a, int b){ return a < b ? a : b; }
__device__ __forceinline__ uint32_t pkhf(float a, float b){
    __half2 h = __floats2half2_rn(a, b);
    return *(uint32_t*)&h;
}
__device__ __forceinline__ u64 pk2(float a, float b){
    u64 r; asm("mov.b64 %0,{%1,%2};" : "=l"(r) : "f"(a), "f"(b)); return r;
}
__device__ __forceinline__ void ff2(u64 &d, u64 a, u64 b){
    asm("fma.rn.f32x2 %0,%1,%2,%0;" : "+l"(d) : "l"(a), "l"(b));
}
__device__ __forceinline__ float2 up2(u64 v){
    float2 r; asm("mov.b64 {%0,%1},%2;" : "=f"(r.x), "=f"(r.y) : "l"(v)); return r;
}

// ============================================================
// prep: V transposed [col][NNP kv], fp16
// ============================================================
__global__ __launch_bounds__(256) void prep_vt(const float* __restrict__ normal){
    int idx = blockIdx.x*256 + threadIdx.x;
    if (idx < TD*NNP){
        int n = idx >> 11, kv = idx & (NNP-1);
        float v = (kv < NN) ? normal[(size_t)kv*TD + n] : 0.f;
        g_vtf[idx] = __float2half_rn(v);
    }
}

// ============================================================
// Kernel 1: q1/k1 = LN(xf@W + b) -> fp16
// ============================================================
#define K1_ROWS 64
#define W_CH 32
#define N_CH (TD / W_CH)
#define K1_XS 0
#define K1_WS 24576
#define K1_QK 32768
#define K1_MU 40960
#define K1_RS 41088
#define K1_SM_BYTES (41216*4)

__device__ __forceinline__ void k1_prefetch_w(float* ws, int tid, int c,
        const float* Wq, const float* Wk)
{
    if (c < N_CH) {
        float* dst = ws + (c & 1) * (W_CH * 128);
        int c0 = c * W_CH;
#pragma unroll
        for (int j = 0; j < 2; j++) {
            int idx = tid + j*512;
            int row = idx >> 5, c4 = idx & 31;
            const float* src = (c4 < 16)
                ? (Wq + (size_t)(c0 + row)*E + c4*4)
                : (Wk + (size_t)(c0 + row)*E + (c4 - 16)*4);
            cpa16(cvta_s(dst + row*128 + ((c4 < 16) ? c4*4 : 64 + (c4-16)*4)), src);
        }
    }
    CP_COMMIT();
}

__global__ __launch_bounds__(512, 1) void qk_ln_kernel(
    const float* __restrict__ x,
    const float* __restrict__ Wq, const float* __restrict__ bq,
    const float* __restrict__ Wk, const float* __restrict__ bk,
    const float* __restrict__ g0, const float* __restrict__ beta0,
    const float* __restrict__ g1, const float* __restrict__ beta1)
{
    extern __shared__ float sm1[];
    float* xs = sm1 + K1_XS;
    float* ws = sm1 + K1_WS;
    float* qk = sm1 + K1_QK;
    float* mu_sh = sm1 + K1_MU;
    float* rs_sh = sm1 + K1_RS;
    const int tid = threadIdx.x;
    const long base = (long)blockIdx.x * K1_ROWS;

    k1_prefetch_w(ws, tid, 0, Wq, Wk);
    k1_prefetch_w(ws, tid, 1, Wq, Wk);

    const float4* xp4 = (const float4*)(x + base*TD);
#pragma unroll
    for (int i = 0; i < 12; i++) ((float4*)xs)[tid + i*512] = xp4[tid + i*512];

    const int col = tid & 63;
    const int grp = tid >> 6;
    const int isK = grp >> 2;
    const int r0  = (grp & 3) * 16;
    const int wcol = isK*64 + col;

    u64 acc2[16];
#pragma unroll
    for (int r = 0; r < 16; r++) acc2[r] = 0ull;

    for (int c = 0; c < N_CH; c++) {
        const float* wb = ws + (c & 1) * (W_CH * 128);
        asm volatile("cp.async.wait_group 1;");
        __syncthreads();
#pragma unroll
        for (int i4l = 0; i4l < W_CH/4; i4l++) {
            int i4 = c*(W_CH/4) + i4l;
            u64 wa = pk2(wb[(i4l*4+0)*128+wcol], wb[(i4l*4+1)*128+wcol]);
            u64 wbp = pk2(wb[(i4l*4+2)*128+wcol], wb[(i4l*4+3)*128+wcol]);
#pragma unroll
            for (int r = 0; r < 16; r++) {
                ulonglong2 xv = ((const ulonglong2*)(xs + (r0 + r)*TD))[i4];
                ff2(acc2[r], xv.x, wa);
                ff2(acc2[r], xv.y, wbp);
            }
        }
        __syncthreads();
        k1_prefetch_w(ws, tid, c + 2, Wq, Wk);
    }

    const float bias = isK ? bk[col] : bq[col];
#pragma unroll
    for (int r = 0; r < 16; r++) {
        float2 f = up2(acc2[r]);
        qk[(r0 + r)*128 + isK*64 + col] = f.x + f.y + bias;
    }
    __syncthreads();

    if (tid < 128) {
        int r = tid & 63, h = tid >> 6;
        const float* v = qk + r*128 + h*64;
        float s = 0.f, s2 = 0.f;
#pragma unroll
        for (int j = 0; j < 64; j++) { float t = v[(j + r) & 63]; s += t; s2 += t*t; }
        float mu = s * (1.f/64.f);
        mu_sh[tid] = mu;
        rs_sh[tid] = rsqrtf(s2*(1.f/64.f) - mu*mu + 1e-5f);
    }
    __syncthreads();

    const float gg = isK ? g1[col] : g0[col];
    const float bb = isK ? beta1[col] : beta0[col];
    __half* __restrict__ oh = isK ? g_kf : g_qf;
#pragma unroll
    for (int r = 0; r < 16; r++) {
        float mu = mu_sh[isK*64 + r0 + r], rs = rs_sh[isK*64 + r0 + r];
        float val = (qk[(r0 + r)*128 + isK*64 + col] - mu) * rs * gg + bb;
        oh[(size_t)(base + r0 + r)*E + col] = __float2half_rn(val);
    }
}

// ============================================================
// Kernel 2: warp-level fp16 mma.sync flash attention (single term)
// BR=128 rows/CTA, 256 threads = 8 warps. Warp w: rows w*16..+15,
// all 32 kv (S) and all 384 out cols (PV). Register epilogue.
// ============================================================
__device__ __forceinline__ void att_prefetch(char* smem, int tid, int t, int b){
    if (t < NTK){
        int st = t & 1;
        {                                        // K: 256 chunks
            int kv = tid >> 3, ch = tid & 7;
            int g = imin(t*BC + kv, NN-1);
            const __half* src = g_kf + ((size_t)b*NN + g)*E + ch*8;
            cpa16(cvta_s(smem + OFF_K + st*KTILE + kv*144 + ch*16), src);
        }
#pragma unroll
        for (int j = 0; j < 6; j++){             // V: 1536 chunks
            int c = tid + j*256;
            int col = c >> 2, ch = c & 3;
            const __half* src = g_vtf + (size_t)col*NNP + t*BC + ch*8;
            cpa16(cvta_s(smem + OFF_V + st*VTILE + col*80 + ch*16), src);
        }
    }
    CP_COMMIT();
}

__global__ __launch_bounds__(256, 1) void attn_mma(
    const float* __restrict__ x,
    const float* __restrict__ Win,
    float* __restrict__ out)
{
    extern __shared__ char smem[];
    const int tid = threadIdx.x;
    const int wid = tid >> 5, lane = tid & 31;
    const int gid = lane >> 2, tig = lane & 3;
    const int b = blockIdx.y;
    const int n0 = blockIdx.x * BR;
    const int r0 = wid * 16;
    const float scale = 0.022360679774997897f;   // 1/sqrt(2000)

    // ---- prologue: Q tile into smem via cp.async (1024 chunks)
#pragma unroll
    for (int j = 0; j < 4; j++){
        int c = tid + j*256;
        int row = c >> 3, ch = c & 7;
        int g = imin(n0 + row, NN-1);
        const __half* src = g_qf + ((size_t)b*NN + g)*E + ch*8;
        cpa16(cvta_s(smem + OFF_Q + row*144 + ch*16), src);
    }
    att_prefetch(smem, tid, 0, b);   // commits {Q + tile0}
    att_prefetch(smem, tid, 1, b);

    float dacc[48][4];
#pragma unroll
    for (int nt = 0; nt < 48; nt++)
#pragma unroll
        for (int c = 0; c < 4; c++) dacc[nt][c] = 0.f;
    float lA = 0.f, lB = 0.f;

    const uint32_t* qf_s = (const uint32_t*)(smem + OFF_Q);
    uint32_t* php = (uint32_t*)(smem + OFF_P);

    for (int t = 0; t < NTK; t++){
        const int st = t & 1;
        asm volatile("cp.async.wait_group 1;");
        __syncthreads();

        // ---- S = Q.K (warp: 16 rows x 32 kv, 16 MMAs)
        float sacc[4][4];
#pragma unroll
        for (int nt = 0; nt < 4; nt++)
#pragma unroll
            for (int c = 0; c < 4; c++) sacc[nt][c] = 0.f;
        {
            const uint32_t* kh = (const uint32_t*)(smem + OFF_K + st*KTILE);
#pragma unroll
            for (int ks = 0; ks < 4; ks++){
                int qa = (r0 + gid)*36 + ks*8 + tig;
                int qb = qa + 8*36;
                uint32_t ah[4] = { qf_s[qa], qf_s[qb], qf_s[qa+4], qf_s[qb+4] };
#pragma unroll
                for (int nt = 0; nt < 4; nt++){
                    int kb = (nt*8 + gid)*36 + ks*8 + tig;
                    uint32_t bh[2] = { kh[kb], kh[kb+4] };
                    mma16816h(sacc[nt], ah, bh);
                }
            }
        }

        // ---- exp + store P (fp16)
#pragma unroll
        for (int nt = 0; nt < 4; nt++){
            int colg = t*BC + nt*8 + tig*2;
            bool m0 = colg < NN, m1 = (colg + 1) < NN;
            float p0 = m0 ? fexp(sacc[nt][0]*scale) : 0.f;
            float p1 = m1 ? fexp(sacc[nt][1]*scale) : 0.f;
            float p2 = m0 ? fexp(sacc[nt][2]*scale) : 0.f;
            float p3 = m1 ? fexp(sacc[nt][3]*scale) : 0.f;
            lA += p0 + p1; lB += p2 + p3;
            int wa = (r0 + gid)*20 + nt*4 + tig;
            int wb = wa + 8*20;
            php[wa] = pkhf(p0, p1);
            php[wb] = pkhf(p2, p3);
        }
        __syncthreads();

        // ---- PV: dacc += P.V (48 n-tiles x 2 k-steps, 96 MMAs)
        {
            const uint32_t* vh = (const uint32_t*)(smem + OFF_V + st*VTILE);
#pragma unroll
            for (int ks = 0; ks < 2; ks++){
                int ra = (r0 + gid)*20 + ks*8 + tig;
                int rb = ra + 8*20;
                uint32_t pah[4] = { php[ra], php[rb], php[ra+4], php[rb+4] };
#pragma unroll
                for (int nt = 0; nt < 48; nt++){
                    int vb = (nt*8 + gid)*20 + ks*8 + tig;
                    uint32_t bh[2] = { vh[vb], vh[vb+4] };
                    mma16816h(dacc[nt], pah, bh);
                }
            }
        }
        __syncthreads();
        att_prefetch(smem, tid, t + 2, b);
    }

    // ---- l: reduce over the quad (tig)
    lA += __shfl_xor_sync(0xffffffffu, lA, 1);
    lA += __shfl_xor_sync(0xffffffffu, lA, 2);
    lB += __shfl_xor_sync(0xffffffffu, lB, 1);
    lB += __shfl_xor_sync(0xffffffffu, lB, 2);
    const float invA = 1.f / lA;
    const float invB = 1.f / lB;

    // ---- q16 = x[b, n, 23, :] @ Win for my two rows
    const int nA = imin(n0 + r0 + gid, NN-1);
    const int nB = imin(n0 + r0 + gid + 8, NN-1);
    float q16A[DD], q16B[DD];
    {
        const float* xa = x + ((size_t)b*NN + nA)*TD + (TT-1)*DD;
        const float* xb = x + ((size_t)b*NN + nB)*TD + (TT-1)*DD;
#pragma unroll
        for (int dp = 0; dp < DD; dp++){
            float sa = 0.f, sb = 0.f;
#pragma unroll
            for (int d = 0; d < DD; d++){
                float w = Win[d*DD + dp];
                sa = fmaf(xa[d], w, sa);
                sb = fmaf(xb[d], w, sb);
            }
            q16A[dp] = sa; q16B[dp] = sb;
        }
    }

    // ---- att scores per t2 (each lane: 4 of 16 d-cols; quad-reduce)
    float wAr[TT], wBr[TT];
#pragma unroll
    for (int t2 = 0; t2 < TT; t2++){
        int nt0 = 2*t2, nt1 = nt0 + 1;
        float aA = q16A[tig*2]   * dacc[nt0][0] + q16A[tig*2+1]   * dacc[nt0][1]
                 + q16A[8+tig*2] * dacc[nt1][0] + q16A[9+tig*2]   * dacc[nt1][1];
        float aB = q16B[tig*2]   * dacc[nt0][2] + q16B[tig*2+1]   * dacc[nt0][3]
                 + q16B[8+tig*2] * dacc[nt1][2] + q16B[9+tig*2]   * dacc[nt1][3];
        aA += __shfl_xor_sync(0xffffffffu, aA, 1);
        aA += __shfl_xor_sync(0xffffffffu, aA, 2);
        aB += __shfl_xor_sync(0xffffffffu, aB, 1);
        aB += __shfl_xor_sync(0xffffffffu, aB, 2);
        wAr[t2] = aA * invA;
        wBr[t2] = aB * invB;
    }
    // softmax over 24
    {
        float mA = -1e30f, mB = -1e30f;
#pragma unroll
        for (int t2 = 0; t2 < TT; t2++){ mA = fmaxf(mA, wAr[t2]); mB = fmaxf(mB, wBr[t2]); }
        float sA = 0.f, sB = 0.f;
#pragma unroll
        for (int t2 = 0; t2 < TT; t2++){
            float eA = __expf(wAr[t2] - mA); wAr[t2] = eA; sA += eA;
            float eB = __expf(wBr[t2] - mB); wBr[t2] = eB; sB += eB;
        }
        float iA = 1.f / sA, iB = 1.f / sB;
#pragma unroll
        for (int t2 = 0; t2 < TT; t2++){ wAr[t2] *= iA; wBr[t2] *= iB; }
    }

    // ---- out = data/l + weight
    const bool vA = (n0 + r0 + gid) < NN;
    const bool vB = (n0 + r0 + gid + 8) < NN;
    float* orowA = out + ((size_t)b*NN + nA)*TD;
    float* orowB = out + ((size_t)b*NN + nB)*TD;
#pragma unroll
    for (int nt = 0; nt < 48; nt++){
        int col = nt*8 + tig*2;
        int t2 = nt >> 1;
        if (vA){
            float2 v; v.x = fmaf(dacc[nt][0], invA, wAr[t2]);
            v.y = fmaf(dacc[nt][1], invA, wAr[t2]);
            *(float2*)(orowA + col) = v;
        }
        if (vB){
            float2 v; v.x = fmaf(dacc[nt][2], invB, wBr[t2]);
            v.y = fmaf(dacc[nt][3], invB, wBr[t2]);
            *(float2*)(orowB + col) = v;
        }
    }
}

// ============================================================
extern "C" void kernel_launch(void* const* d_in, const int* in_sizes, int n_in,
                              void* d_out, int out_size)
{
    (void)in_sizes; (void)n_in; (void)out_size;
    const float* x     = (const float*)d_in[0];
    const float* Wq    = (const float*)d_in[1];
    const float* bq    = (const float*)d_in[2];
    const float* Wk    = (const float*)d_in[3];
    const float* bk    = (const float*)d_in[4];
    const float* g0    = (const float*)d_in[5];
    const float* beta0 = (const float*)d_in[6];
    const float* g1    = (const float*)d_in[7];
    const float* beta1 = (const float*)d_in[8];
    const float* nrm   = (const float*)d_in[9];
    const float* Win   = (const float*)d_in[10];
    float* out = (float*)d_out;

    cudaFuncSetAttribute(qk_ln_kernel, cudaFuncAttributeMaxDynamicSharedMemorySize, K1_SM_BYTES);
    cudaFuncSetAttribute(attn_mma,     cudaFuncAttributeMaxDynamicSharedMemorySize, SMEM_ATT);

    prep_vt<<<(TD*NNP + 255)/256, 256>>>(nrm);
    qk_ln_kernel<<<(B*NN)/K1_ROWS, 512, K1_SM_BYTES>>>(x, Wq, bq, Wk, bk, g0, beta0, g1, beta1);

    dim3 grid((NN + BR - 1)/BR, B);
    attn_mma<<<grid, 256, SMEM_ATT>>>(x, Win, out);
}

// round 12
// speedup vs baseline: 2.5413x; 1.2657x over previous
#include <cuda_runtime.h>
#include <cuda_fp16.h>
#include <cstdint>

#define B    32
#define NN   2000
#define TD   384
#define E    64
#define TT   24
#define DD   16
#define NNP  2048

#define BR   128
#define BC   32
#define NTK  63

// ---- attn smem byte layout (fp16, single term)
#define OFF_Q   0            // 128 rows x 144B = 18432
#define OFF_K   18432        // 2 stages x 32 x 144B = 9216
#define KTILE   4608
#define OFF_V   27648        // 2 stages x 384 x 80B = 61440
#define VTILE   30720
#define OFF_P   89088        // 128 rows x 80B = 10240
#define SMEM_ATT 99328

// ---- k1 tensor-GEMM layout
#define K1M     128
#define K1_XST  68           // uints per 272B row
#define K1_XTILE 34816       // 128 rows x 272B
#define K1_OFF_X 0           // 2 stages
#define K1_OFF_W 69632       // 3 chunks x 34816 = 104448
#define K1_OFF_C 174080      // 384 floats (bias|gamma|beta x128)
#define K1_SMEM  175616

typedef unsigned long long u64;

__device__ __align__(16) __half g_qf[B*NN*E];
__device__ __align__(16) __half g_kf[B*NN*E];
__device__ __align__(16) __half g_vtf[TD*NNP];
__device__ __align__(16) __half g_xh[B*NN*TD];
__device__ __align__(16) __half g_wt[3*128*136];   // [chunk][n][136]

// =================== helpers ===================
__device__ __forceinline__ uint32_t cvta_s(const void* p){
    return (uint32_t)__cvta_generic_to_shared(p);
}
__device__ __forceinline__ void cpa16(uint32_t d, const void* s){
    asm volatile("cp.async.cg.shared.global [%0],[%1],16;" :: "r"(d), "l"(s));
}
#define CP_COMMIT() asm volatile("cp.async.commit_group;")

__device__ __forceinline__ void mma16816h(float* d, const uint32_t* a, const uint32_t* b){
    asm volatile("mma.sync.aligned.m16n8k16.row.col.f32.f16.f16.f32 "
        "{%0,%1,%2,%3},{%4,%5,%6,%7},{%8,%9},{%0,%1,%2,%3};"
        : "+f"(d[0]), "+f"(d[1]), "+f"(d[2]), "+f"(d[3])
        : "r"(a[0]), "r"(a[1]), "r"(a[2]), "r"(a[3]), "r"(b[0]), "r"(b[1]));
}

__device__ __forceinline__ float fexp(float x){   // valid |x| <= ~3
    float t = x * 1.4426950408889634f;
    float c = t + 12582912.f;
    int k = __float_as_int(c) - 0x4B400000;
    float f = t - (c - 12582912.f);
    float z = f * 0.6931471805599453f;
    float p = fmaf(z, 0.0083333333f, 0.0416666667f);
    p = fmaf(p, z, 0.1666666667f);
    p = fmaf(p, z, 0.5f);
    p = fmaf(p, z, 1.0f);
    p = fmaf(p, z, 1.0f);
    return __int_as_float(__float_as_int(p) + (k << 23));
}
__device__ __forceinline__ int imin(int a, int b){ return a < b ? a : b; }
__device__ __forceinline__ uint32_t pkhf(float a, float b){
    __half2 h = __floats2half2_rn(a, b);
    return *(uint32_t*)&h;
}

// ============================================================
// prep kernels
// ============================================================
__global__ __launch_bounds__(256) void prep_vt(const float* __restrict__ normal){
    int idx = blockIdx.x*256 + threadIdx.x;
    if (idx < TD*NNP){
        int n = idx >> 11, kv = idx & (NNP-1);
        float v = (kv < NN) ? normal[(size_t)kv*TD + n] : 0.f;
        g_vtf[idx] = __float2half_rn(v);
    }
}

__global__ __launch_bounds__(256) void prep_x(const float* __restrict__ x){
    int idx = blockIdx.x*256 + threadIdx.x;     // over float4s: 6,144,000
    if (idx < (B*NN*TD)/4){
        float4 v = ((const float4*)x)[idx];
        uint2 o;
        o.x = pkhf(v.x, v.y);
        o.y = pkhf(v.z, v.w);
        ((uint2*)g_xh)[idx] = o;
    }
}

__global__ __launch_bounds__(256) void prep_wt(const float* __restrict__ Wq,
                                               const float* __restrict__ Wk){
    int idx = blockIdx.x*256 + threadIdx.x;     // over 3*128*136 = 52224
    if (idx < 3*128*136){
        int c = idx / (128*136);
        int rem = idx - c*(128*136);
        int n = rem / 136, kk = rem - n*136;
        float v = 0.f;
        if (kk < 128){
            int k = c*128 + kk;
            v = (n < 64) ? Wq[k*64 + n] : Wk[k*64 + (n - 64)];
        }
        g_wt[idx] = __float2half_rn(v);
    }
}

// ============================================================
// Kernel 1: y = xh @ W (fp16 HMMA), + bias, LN per 64-col half,
// -> g_qf / g_kf.  128 rows/CTA, 256 threads, warp = 16 rows x 128 cols.
// ============================================================
__device__ __forceinline__ void k1_prefx(char* sm, int tid, long base, int c, int s){
#pragma unroll
    for (int j = 0; j < 8; j++){
        int idx = tid + j*256;                  // 2048 chunks
        int row = idx >> 4, ch = idx & 15;
        const __half* src = g_xh + (base + row)*(size_t)TD + c*128 + ch*8;
        cpa16(cvta_s(sm + K1_OFF_X + s*K1_XTILE + row*272 + ch*16), src);
    }
    CP_COMMIT();
}

__global__ __launch_bounds__(256, 1) void k1_tc(
    const float* __restrict__ bq, const float* __restrict__ bk,
    const float* __restrict__ g0, const float* __restrict__ beta0,
    const float* __restrict__ g1, const float* __restrict__ beta1)
{
    extern __shared__ char sm[];
    const int tid = threadIdx.x;
    const int wid = tid >> 5, lane = tid & 31;
    const int gid = lane >> 2, tig = lane & 3;
    const int r0 = wid * 16;
    const long base = (long)blockIdx.x * K1M;   // 500 CTAs exact

    // stage constants: [bias|gamma|beta] x 128 cols
    float* cs = (float*)(sm + K1_OFF_C);
    if (tid < 128){
        cs[tid]       = (tid < 64) ? bq[tid] : bk[tid - 64];
        cs[128 + tid] = (tid < 64) ? g0[tid] : g1[tid - 64];
        cs[256 + tid] = (tid < 64) ? beta0[tid] : beta1[tid - 64];
    }

    k1_prefx(sm, tid, base, 0, 0);              // G0
    {   // W flat copy: 6528 x 16B              // G1
#pragma unroll
        for (int j = 0; j < 26; j++){
            int i = tid + j*256;
            if (i < 6528)
                cpa16(cvta_s(sm + K1_OFF_W + i*16), (const char*)g_wt + i*16);
        }
        CP_COMMIT();
    }
    k1_prefx(sm, tid, base, 1, 1);              // G2

    float acc[16][4];
#pragma unroll
    for (int nt = 0; nt < 16; nt++)
#pragma unroll
        for (int j = 0; j < 4; j++) acc[nt][j] = 0.f;

#pragma unroll
    for (int c = 0; c < 3; c++){
        if (c < 2) asm volatile("cp.async.wait_group 1;");
        else       asm volatile("cp.async.wait_group 0;");
        __syncthreads();
        const uint32_t* xs  = (const uint32_t*)(sm + K1_OFF_X + (c & 1)*K1_XTILE);
        const uint32_t* wsp = (const uint32_t*)(sm + K1_OFF_W + c*K1_XTILE);
#pragma unroll
        for (int ks = 0; ks < 8; ks++){
            int qa = (r0 + gid)*K1_XST + ks*8 + tig;
            int qb = qa + 8*K1_XST;
            uint32_t a[4] = { xs[qa], xs[qb], xs[qa+4], xs[qb+4] };
#pragma unroll
            for (int nt = 0; nt < 16; nt++){
                int kb = (nt*8 + gid)*K1_XST + ks*8 + tig;
                uint32_t bfr[2] = { wsp[kb], wsp[kb+4] };
                mma16816h(acc[nt], a, bfr);
            }
        }
        __syncthreads();
        if (c == 0){ k1_prefx(sm, tid, base, 2, 0); }
    }

    // ---- epilogue: +bias, LN per half, write fp16
    const int c0 = tig*2;
#pragma unroll
    for (int nt = 0; nt < 16; nt++){
        int col = (nt < 8) ? nt*8 + c0 : 64 + (nt - 8)*8 + c0;
        float b0 = cs[col], b1 = cs[col + 1];
        acc[nt][0] += b0; acc[nt][1] += b1;
        acc[nt][2] += b0; acc[nt][3] += b1;
    }
    float sqA=0,ssA=0,skA=0,sskA=0, sqB=0,ssB=0,skB=0,sskB=0;
#pragma unroll
    for (int nt = 0; nt < 8; nt++){
        sqA += acc[nt][0] + acc[nt][1];
        ssA += acc[nt][0]*acc[nt][0] + acc[nt][1]*acc[nt][1];
        sqB += acc[nt][2] + acc[nt][3];
        ssB += acc[nt][2]*acc[nt][2] + acc[nt][3]*acc[nt][3];
    }
#pragma unroll
    for (int nt = 8; nt < 16; nt++){
        skA += acc[nt][0] + acc[nt][1];
        sskA += acc[nt][0]*acc[nt][0] + acc[nt][1]*acc[nt][1];
        skB += acc[nt][2] + acc[nt][3];
        sskB += acc[nt][2]*acc[nt][2] + acc[nt][3]*acc[nt][3];
    }
#pragma unroll
    for (int off = 1; off <= 2; off <<= 1){
        sqA += __shfl_xor_sync(0xffffffffu, sqA, off);
        ssA += __shfl_xor_sync(0xffffffffu, ssA, off);
        skA += __shfl_xor_sync(0xffffffffu, skA, off);
        sskA += __shfl_xor_sync(0xffffffffu, sskA, off);
        sqB += __shfl_xor_sync(0xffffffffu, sqB, off);
        ssB += __shfl_xor_sync(0xffffffffu, ssB, off);
        skB += __shfl_xor_sync(0xffffffffu, skB, off);
        sskB += __shfl_xor_sync(0xffffffffu, sskB, off);
    }
    const float inv64 = 1.f/64.f;
    float muqA = sqA*inv64, rsqA = rsqrtf(ssA*inv64 - muqA*muqA + 1e-5f);
    float muqB = sqB*inv64, rsqB = rsqrtf(ssB*inv64 - muqB*muqB + 1e-5f);
    float mukA = skA*inv64, rskA = rsqrtf(sskA*inv64 - mukA*mukA + 1e-5f);
    float mukB = skB*inv64, rskB = rsqrtf(sskB*inv64 - mukB*mukB + 1e-5f);

    const size_t rowA = (size_t)(base + r0 + gid);
    const size_t rowB = rowA + 8;
#pragma unroll
    for (int nt = 0; nt < 8; nt++){
        int col = nt*8 + c0;
        float ga = cs[128 + col], gb = cs[128 + col + 1];
        float ba = cs[256 + col], bb = cs[256 + col + 1];
        *(uint32_t*)(g_qf + rowA*E + col) =
            pkhf((acc[nt][0]-muqA)*rsqA*ga + ba, (acc[nt][1]-muqA)*rsqA*gb + bb);
        *(uint32_t*)(g_qf + rowB*E + col) =
            pkhf((acc[nt][2]-muqB)*rsqB*ga + ba, (acc[nt][3]-muqB)*rsqB*gb + bb);
    }
#pragma unroll
    for (int nt = 8; nt < 16; nt++){
        int col = (nt - 8)*8 + c0;
        float ga = cs[128 + 64 + col], gb = cs[128 + 64 + col + 1];
        float ba = cs[256 + 64 + col], bb = cs[256 + 64 + col + 1];
        *(uint32_t*)(g_kf + rowA*E + col) =
            pkhf((acc[nt][0]-mukA)*rskA*ga + ba, (acc[nt][1]-mukA)*rskA*gb + bb);
        *(uint32_t*)(g_kf + rowB*E + col) =
            pkhf((acc[nt][2]-mukB)*rskB*ga + ba, (acc[nt][3]-mukB)*rskB*gb + bb);
    }
}

// ============================================================
// Kernel 2: warp-level fp16 mma.sync flash attention (unchanged from R11)
// ============================================================
__device__ __forceinline__ void att_prefetch(char* smem, int tid, int t, int b){
    if (t < NTK){
        int st = t & 1;
        {
            int kv = tid >> 3, ch = tid & 7;
            int g = imin(t*BC + kv, NN-1);
            const __half* src = g_kf + ((size_t)b*NN + g)*E + ch*8;
            cpa16(cvta_s(smem + OFF_K + st*KTILE + kv*144 + ch*16), src);
        }
#pragma unroll
        for (int j = 0; j < 6; j++){
            int c = tid + j*256;
            int col = c >> 2, ch = c & 3;
            const __half* src = g_vtf + (size_t)col*NNP + t*BC + ch*8;
            cpa16(cvta_s(smem + OFF_V + st*VTILE + col*80 + ch*16), src);
        }
    }
    CP_COMMIT();
}

__global__ __launch_bounds__(256, 1) void attn_mma(
    const float* __restrict__ x,
    const float* __restrict__ Win,
    float* __restrict__ out)
{
    extern __shared__ char smem[];
    const int tid = threadIdx.x;
    const int wid = tid >> 5, lane = tid & 31;
    const int gid = lane >> 2, tig = lane & 3;
    const int b = blockIdx.y;
    const int n0 = blockIdx.x * BR;
    const int r0 = wid * 16;
    const float scale = 0.022360679774997897f;

#pragma unroll
    for (int j = 0; j < 4; j++){
        int c = tid + j*256;
        int row = c >> 3, ch = c & 7;
        int g = imin(n0 + row, NN-1);
        const __half* src = g_qf + ((size_t)b*NN + g)*E + ch*8;
        cpa16(cvta_s(smem + OFF_Q + row*144 + ch*16), src);
    }
    att_prefetch(smem, tid, 0, b);
    att_prefetch(smem, tid, 1, b);

    float dacc[48][4];
#pragma unroll
    for (int nt = 0; nt < 48; nt++)
#pragma unroll
        for (int c = 0; c < 4; c++) dacc[nt][c] = 0.f;
    float lA = 0.f, lB = 0.f;

    const uint32_t* qf_s = (const uint32_t*)(smem + OFF_Q);
    uint32_t* php = (uint32_t*)(smem + OFF_P);

    for (int t = 0; t < NTK; t++){
        const int st = t & 1;
        asm volatile("cp.async.wait_group 1;");
        __syncthreads();

        float sacc[4][4];
#pragma unroll
        for (int nt = 0; nt < 4; nt++)
#pragma unroll
            for (int c = 0; c < 4; c++) sacc[nt][c] = 0.f;
        {
            const uint32_t* kh = (const uint32_t*)(smem + OFF_K + st*KTILE);
#pragma unroll
            for (int ks = 0; ks < 4; ks++){
                int qa = (r0 + gid)*36 + ks*8 + tig;
                int qb = qa + 8*36;
                uint32_t ah[4] = { qf_s[qa], qf_s[qb], qf_s[qa+4], qf_s[qb+4] };
#pragma unroll
                for (int nt = 0; nt < 4; nt++){
                    int kb = (nt*8 + gid)*36 + ks*8 + tig;
                    uint32_t bh[2] = { kh[kb], kh[kb+4] };
                    mma16816h(sacc[nt], ah, bh);
                }
            }
        }

#pragma unroll
        for (int nt = 0; nt < 4; nt++){
            int colg = t*BC + nt*8 + tig*2;
            bool m0 = colg < NN, m1 = (colg + 1) < NN;
            float p0 = m0 ? fexp(sacc[nt][0]*scale) : 0.f;
            float p1 = m1 ? fexp(sacc[nt][1]*scale) : 0.f;
            float p2 = m0 ? fexp(sacc[nt][2]*scale) : 0.f;
            float p3 = m1 ? fexp(sacc[nt][3]*scale) : 0.f;
            lA += p0 + p1; lB += p2 + p3;
            int wa = (r0 + gid)*20 + nt*4 + tig;
            int wb = wa + 8*20;
            php[wa] = pkhf(p0, p1);
            php[wb] = pkhf(p2, p3);
        }
        __syncthreads();

        {
            const uint32_t* vh = (const uint32_t*)(smem + OFF_V + st*VTILE);
#pragma unroll
            for (int ks = 0; ks < 2; ks++){
                int ra = (r0 + gid)*20 + ks*8 + tig;
                int rb = ra + 8*20;
                uint32_t pah[4] = { php[ra], php[rb], php[ra+4], php[rb+4] };
#pragma unroll
                for (int nt = 0; nt < 48; nt++){
                    int vb = (nt*8 + gid)*20 + ks*8 + tig;
                    uint32_t bh[2] = { vh[vb], vh[vb+4] };
                    mma16816h(dacc[nt], pah, bh);
                }
            }
        }
        __syncthreads();
        att_prefetch(smem, tid, t + 2, b);
    }

    lA += __shfl_xor_sync(0xffffffffu, lA, 1);
    lA += __shfl_xor_sync(0xffffffffu, lA, 2);
    lB += __shfl_xor_sync(0xffffffffu, lB, 1);
    lB += __shfl_xor_sync(0xffffffffu, lB, 2);
    const float invA = 1.f / lA;
    const float invB = 1.f / lB;

    const int nA = imin(n0 + r0 + gid, NN-1);
    const int nB = imin(n0 + r0 + gid + 8, NN-1);
    float q16A[DD], q16B[DD];
    {
        const float* xa = x + ((size_t)b*NN + nA)*TD + (TT-1)*DD;
        const float* xb = x + ((size_t)b*NN + nB)*TD + (TT-1)*DD;
#pragma unroll
        for (int dp = 0; dp < DD; dp++){
            float sa = 0.f, sb = 0.f;
#pragma unroll
            for (int d = 0; d < DD; d++){
                float w = Win[d*DD + dp];
                sa = fmaf(xa[d], w, sa);
                sb = fmaf(xb[d], w, sb);
            }
            q16A[dp] = sa; q16B[dp] = sb;
        }
    }

    float wAr[TT], wBr[TT];
#pragma unroll
    for (int t2 = 0; t2 < TT; t2++){
        int nt0 = 2*t2, nt1 = nt0 + 1;
        float aA = q16A[tig*2]   * dacc[nt0][0] + q16A[tig*2+1]   * dacc[nt0][1]
                 + q16A[8+tig*2] * dacc[nt1][0] + q16A[9+tig*2]   * dacc[nt1][1];
        float aB = q16B[tig*2]   * dacc[nt0][2] + q16B[tig*2+1]   * dacc[nt0][3]
                 + q16B[8+tig*2] * dacc[nt1][2] + q16B[9+tig*2]   * dacc[nt1][3];
        aA += __shfl_xor_sync(0xffffffffu, aA, 1);
        aA += __shfl_xor_sync(0xffffffffu, aA, 2);
        aB += __shfl_xor_sync(0xffffffffu, aB, 1);
        aB += __shfl_xor_sync(0xffffffffu, aB, 2);
        wAr[t2] = aA * invA;
        wBr[t2] = aB * invB;
    }
    {
        float mA = -1e30f, mB = -1e30f;
#pragma unroll
        for (int t2 = 0; t2 < TT; t2++){ mA = fmaxf(mA, wAr[t2]); mB = fmaxf(mB, wBr[t2]); }
        float sA = 0.f, sB = 0.f;
#pragma unroll
        for (int t2 = 0; t2 < TT; t2++){
            float eA = __expf(wAr[t2] - mA); wAr[t2] = eA; sA += eA;
            float eB = __expf(wBr[t2] - mB); wBr[t2] = eB; sB += eB;
        }
        float iA = 1.f / sA, iB = 1.f / sB;
#pragma unroll
        for (int t2 = 0; t2 < TT; t2++){ wAr[t2] *= iA; wBr[t2] *= iB; }
    }

    const bool vA = (n0 + r0 + gid) < NN;
    const bool vB = (n0 + r0 + gid + 8) < NN;
    float* orowA = out + ((size_t)b*NN + nA)*TD;
    float* orowB = out + ((size_t)b*NN + nB)*TD;
#pragma unroll
    for (int nt = 0; nt < 48; nt++){
        int col = nt*8 + tig*2;
        int t2 = nt >> 1;
        if (vA){
            float2 v; v.x = fmaf(dacc[nt][0], invA, wAr[t2]);
            v.y = fmaf(dacc[nt][1], invA, wAr[t2]);
            *(float2*)(orowA + col) = v;
        }
        if (vB){
            float2 v; v.x = fmaf(dacc[nt][2], invB, wBr[t2]);
            v.y = fmaf(dacc[nt][3], invB, wBr[t2]);
            *(float2*)(orowB + col) = v;
        }
    }
}

// ============================================================
extern "C" void kernel_launch(void* const* d_in, const int* in_sizes, int n_in,
                              void* d_out, int out_size)
{
    (void)in_sizes; (void)n_in; (void)out_size;
    const float* x     = (const float*)d_in[0];
    const float* Wq    = (const float*)d_in[1];
    const float* bq    = (const float*)d_in[2];
    const float* Wk    = (const float*)d_in[3];
    const float* bk    = (const float*)d_in[4];
    const float* g0    = (const float*)d_in[5];
    const float* beta0 = (const float*)d_in[6];
    const float* g1    = (const float*)d_in[7];
    const float* beta1 = (const float*)d_in[8];
    const float* nrm   = (const float*)d_in[9];
    const float* Win   = (const float*)d_in[10];
    float* out = (float*)d_out;

    cudaFuncSetAttribute(k1_tc,    cudaFuncAttributeMaxDynamicSharedMemorySize, K1_SMEM);
    cudaFuncSetAttribute(attn_mma, cudaFuncAttributeMaxDynamicSharedMemorySize, SMEM_ATT);

    prep_vt<<<(TD*NNP + 255)/256, 256>>>(nrm);
    prep_x<<<((B*NN*TD)/4 + 255)/256, 256>>>(x);
    prep_wt<<<(3*128*136 + 255)/256, 256>>>(Wq, Wk);

    k1_tc<<<(B*NN)/K1M, 256, K1_SMEM>>>(bq, bk, g0, beta0, g1, beta1);

    dim3 grid((NN + BR - 1)/BR, B);
    attn_mma<<<grid, 256, SMEM_ATT>>>(x, Win, out);
}

// round 13
// speedup vs baseline: 3.0441x; 1.1978x over previous
#include <cuda_runtime.h>
#include <cuda_fp16.h>
#include <cstdint>

#define B    32
#define NN   2000
#define TD   384
#define E    64
#define TT   24
#define DD   16

#define BR   128
#define BC   32
#define NTK  63

// ---- K/V gmem tile-image geometry (exact smem images, padded strides)
#define KIMG_TILE_B   4608              // 32 rows x 144B
#define KIMG_BATCH_H  145152            // 63 * 2304 halves
#define VIMG_TILE_B   30720             // 384 rows x 80B
#define VIMG_TILE_H   15360

// ---- attn smem byte layout
#define OFF_Q   0                        // 128 rows x 144B = 18432
#define OFF_MB  18432                    // 2 mbarriers (8B each)
#define OFF_ST  18944                    // 2 stages x (K 4608 + V 30720)
#define STG     35328
#define SMEM_ATT (OFF_ST + 2*STG)        // 89600

// ---- k1 tensor-GEMM layout
#define K1M     128
#define K1_XST  68
#define K1_XTILE 34816
#define K1_OFF_X 0
#define K1_OFF_W 69632
#define K1_OFF_C 174080
#define K1_SMEM  175616

typedef unsigned long long u64;

__device__ __align__(16) __half g_qf[B*NN*E];
__device__ __align__(16) __half g_kimg[B*63*2304];     // padded K tile images
__device__ __align__(16) __half g_vimg[63*VIMG_TILE_H];// padded V tile images
__device__ __align__(16) __half g_xh[B*NN*TD];
__device__ __align__(16) __half g_wt[3*128*136];

// =================== helpers ===================
__device__ __forceinline__ uint32_t cvta_s(const void* p){
    return (uint32_t)__cvta_generic_to_shared(p);
}
__device__ __forceinline__ void cpa16(uint32_t d, const void* s){
    asm volatile("cp.async.cg.shared.global [%0],[%1],16;" :: "r"(d), "l"(s));
}
#define CP_COMMIT() asm volatile("cp.async.commit_group;")

__device__ __forceinline__ void mma16816h(float* d, const uint32_t* a, const uint32_t* b){
    asm volatile("mma.sync.aligned.m16n8k16.row.col.f32.f16.f16.f32 "
        "{%0,%1,%2,%3},{%4,%5,%6,%7},{%8,%9},{%0,%1,%2,%3};"
        : "+f"(d[0]), "+f"(d[1]), "+f"(d[2]), "+f"(d[3])
        : "r"(a[0]), "r"(a[1]), "r"(a[2]), "r"(a[3]), "r"(b[0]), "r"(b[1]));
}

__device__ __forceinline__ float fexp(float x){   // valid |x| <= ~3
    float t = x * 1.4426950408889634f;
    float c = t + 12582912.f;
    int k = __float_as_int(c) - 0x4B400000;
    float f = t - (c - 12582912.f);
    float z = f * 0.6931471805599453f;
    float p = fmaf(z, 0.0083333333f, 0.0416666667f);
    p = fmaf(p, z, 0.1666666667f);
    p = fmaf(p, z, 0.5f);
    p = fmaf(p, z, 1.0f);
    p = fmaf(p, z, 1.0f);
    return __int_as_float(__float_as_int(p) + (k << 23));
}
__device__ __forceinline__ int imin(int a, int b){ return a < b ? a : b; }
__device__ __forceinline__ uint32_t pkhf(float a, float b){
    __half2 h = __floats2half2_rn(a, b);
    return *(uint32_t*)&h;
}

__device__ __forceinline__ void mbar_init(uint32_t a, uint32_t cnt){
    asm volatile("mbarrier.init.shared.b64 [%0], %1;" :: "r"(a), "r"(cnt) : "memory");
}
__device__ __forceinline__ void mbar_wait(uint32_t a, uint32_t parity){
    uint32_t done;
    asm volatile("{.reg .pred p; mbarrier.try_wait.parity.acquire.cta.shared::cta.b64 p, [%1], %2; selp.b32 %0,1,0,p;}"
        : "=r"(done) : "r"(a), "r"(parity) : "memory");
    if (!done)
        asm volatile("{.reg .pred P1; WL%=: mbarrier.try_wait.parity.acquire.cta.shared::cta.b64 P1, [%0], %1, 0x989680;"
                     "@P1 bra.uni WD%=; bra.uni WL%=; WD%=: }" :: "r"(a), "r"(parity) : "memory");
}

// ============================================================
// prep kernels
// ============================================================
__global__ __launch_bounds__(256) void prep_vt(const float* __restrict__ normal){
    int idx = blockIdx.x*256 + threadIdx.x;      // 63*384*32 = 774144
    if (idx < 63*384*32){
        int t = idx / (384*32);
        int rem = idx - t*(384*32);
        int n = rem >> 5, j = rem & 31;
        int kv = t*32 + j;
        float v = (kv < NN) ? normal[(size_t)kv*TD + n] : 0.f;
        g_vimg[(size_t)t*VIMG_TILE_H + n*40 + j] = __float2half_rn(v);
    }
}

__global__ __launch_bounds__(256) void prep_x(const float* __restrict__ x){
    int idx = blockIdx.x*256 + threadIdx.x;
    if (idx < (B*NN*TD)/4){
        float4 v = ((const float4*)x)[idx];
        uint2 o;
        o.x = pkhf(v.x, v.y);
        o.y = pkhf(v.z, v.w);
        ((uint2*)g_xh)[idx] = o;
    }
}

__global__ __launch_bounds__(256) void prep_wt(const float* __restrict__ Wq,
                                               const float* __restrict__ Wk){
    int idx = blockIdx.x*256 + threadIdx.x;
    if (idx < 3*128*136){
        int c = idx / (128*136);
        int rem = idx - c*(128*136);
        int n = rem / 136, kk = rem - n*136;
        float v = 0.f;
        if (kk < 128){
            int k = c*128 + kk;
            v = (n < 64) ? Wq[k*64 + n] : Wk[k*64 + (n - 64)];
        }
        g_wt[idx] = __float2half_rn(v);
    }
}

// ============================================================
// Kernel 1: y = xh @ W (fp16 HMMA), +bias, LN -> g_qf / g_kimg
// ============================================================
__device__ __forceinline__ void k1_prefx(char* sm, int tid, long base, int c, int s){
#pragma unroll
    for (int j = 0; j < 8; j++){
        int idx = tid + j*256;
        int row = idx >> 4, ch = idx & 15;
        const __half* src = g_xh + (base + row)*(size_t)TD + c*128 + ch*8;
        cpa16(cvta_s(sm + K1_OFF_X + s*K1_XTILE + row*272 + ch*16), src);
    }
    CP_COMMIT();
}

__global__ __launch_bounds__(256, 1) void k1_tc(
    const float* __restrict__ bq, const float* __restrict__ bk,
    const float* __restrict__ g0, const float* __restrict__ beta0,
    const float* __restrict__ g1, const float* __restrict__ beta1)
{
    extern __shared__ char sm[];
    const int tid = threadIdx.x;
    const int wid = tid >> 5, lane = tid & 31;
    const int gid = lane >> 2, tig = lane & 3;
    const int r0 = wid * 16;
    const long base = (long)blockIdx.x * K1M;

    float* cs = (float*)(sm + K1_OFF_C);
    if (tid < 128){
        cs[tid]       = (tid < 64) ? bq[tid] : bk[tid - 64];
        cs[128 + tid] = (tid < 64) ? g0[tid] : g1[tid - 64];
        cs[256 + tid] = (tid < 64) ? beta0[tid] : beta1[tid - 64];
    }

    k1_prefx(sm, tid, base, 0, 0);
    {
#pragma unroll
        for (int j = 0; j < 26; j++){
            int i = tid + j*256;
            if (i < 6528)
                cpa16(cvta_s(sm + K1_OFF_W + i*16), (const char*)g_wt + i*16);
        }
        CP_COMMIT();
    }
    k1_prefx(sm, tid, base, 1, 1);

    float acc[16][4];
#pragma unroll
    for (int nt = 0; nt < 16; nt++)
#pragma unroll
        for (int j = 0; j < 4; j++) acc[nt][j] = 0.f;

#pragma unroll
    for (int c = 0; c < 3; c++){
        if (c < 2) asm volatile("cp.async.wait_group 1;");
        else       asm volatile("cp.async.wait_group 0;");
        __syncthreads();
        const uint32_t* xs  = (const uint32_t*)(sm + K1_OFF_X + (c & 1)*K1_XTILE);
        const uint32_t* wsp = (const uint32_t*)(sm + K1_OFF_W + c*K1_XTILE);
#pragma unroll
        for (int ks = 0; ks < 8; ks++){
            int qa = (r0 + gid)*K1_XST + ks*8 + tig;
            int qb = qa + 8*K1_XST;
            uint32_t a[4] = { xs[qa], xs[qb], xs[qa+4], xs[qb+4] };
#pragma unroll
            for (int nt = 0; nt < 16; nt++){
                int kb = (nt*8 + gid)*K1_XST + ks*8 + tig;
                uint32_t bfr[2] = { wsp[kb], wsp[kb+4] };
                mma16816h(acc[nt], a, bfr);
            }
        }
        __syncthreads();
        if (c == 0){ k1_prefx(sm, tid, base, 2, 0); }
    }

    const int c0 = tig*2;
#pragma unroll
    for (int nt = 0; nt < 16; nt++){
        int col = (nt < 8) ? nt*8 + c0 : 64 + (nt - 8)*8 + c0;
        float b0 = cs[col], b1 = cs[col + 1];
        acc[nt][0] += b0; acc[nt][1] += b1;
        acc[nt][2] += b0; acc[nt][3] += b1;
    }
    float sqA=0,ssA=0,skA=0,sskA=0, sqB=0,ssB=0,skB=0,sskB=0;
#pragma unroll
    for (int nt = 0; nt < 8; nt++){
        sqA += acc[nt][0] + acc[nt][1];
        ssA += acc[nt][0]*acc[nt][0] + acc[nt][1]*acc[nt][1];
        sqB += acc[nt][2] + acc[nt][3];
        ssB += acc[nt][2]*acc[nt][2] + acc[nt][3]*acc[nt][3];
    }
#pragma unroll
    for (int nt = 8; nt < 16; nt++){
        skA += acc[nt][0] + acc[nt][1];
        sskA += acc[nt][0]*acc[nt][0] + acc[nt][1]*acc[nt][1];
        skB += acc[nt][2] + acc[nt][3];
        sskB += acc[nt][2]*acc[nt][2] + acc[nt][3]*acc[nt][3];
    }
#pragma unroll
    for (int off = 1; off <= 2; off <<= 1){
        sqA += __shfl_xor_sync(0xffffffffu, sqA, off);
        ssA += __shfl_xor_sync(0xffffffffu, ssA, off);
        skA += __shfl_xor_sync(0xffffffffu, skA, off);
        sskA += __shfl_xor_sync(0xffffffffu, sskA, off);
        sqB += __shfl_xor_sync(0xffffffffu, sqB, off);
        ssB += __shfl_xor_sync(0xffffffffu, ssB, off);
        skB += __shfl_xor_sync(0xffffffffu, skB, off);
        sskB += __shfl_xor_sync(0xffffffffu, sskB, off);
    }
    const float inv64 = 1.f/64.f;
    float muqA = sqA*inv64, rsqA = rsqrtf(ssA*inv64 - muqA*muqA + 1e-5f);
    float muqB = sqB*inv64, rsqB = rsqrtf(ssB*inv64 - muqB*muqB + 1e-5f);
    float mukA = skA*inv64, rskA = rsqrtf(sskA*inv64 - mukA*mukA + 1e-5f);
    float mukB = skB*inv64, rskB = rsqrtf(sskB*inv64 - mukB*mukB + 1e-5f);

    const int grA = (int)(base + r0 + gid);
    const int grB = grA + 8;
    const int bA = grA / NN, nAq = grA - bA*NN;
    const int bB = grB / NN, nBq = grB - bB*NN;
    __half* kdstA = g_kimg + (size_t)bA*KIMG_BATCH_H + (nAq >> 5)*2304 + (nAq & 31)*72;
    __half* kdstB = g_kimg + (size_t)bB*KIMG_BATCH_H + (nBq >> 5)*2304 + (nBq & 31)*72;

#pragma unroll
    for (int nt = 0; nt < 8; nt++){
        int col = nt*8 + c0;
        float ga = cs[128 + col], gb = cs[128 + col + 1];
        float ba = cs[256 + col], bb = cs[256 + col + 1];
        *(uint32_t*)(g_qf + (size_t)grA*E + col) =
            pkhf((acc[nt][0]-muqA)*rsqA*ga + ba, (acc[nt][1]-muqA)*rsqA*gb + bb);
        *(uint32_t*)(g_qf + (size_t)grB*E + col) =
            pkhf((acc[nt][2]-muqB)*rsqB*ga + ba, (acc[nt][3]-muqB)*rsqB*gb + bb);
    }
#pragma unroll
    for (int nt = 8; nt < 16; nt++){
        int col = (nt - 8)*8 + c0;
        float ga = cs[128 + 64 + col], gb = cs[128 + 64 + col + 1];
        float ba = cs[256 + 64 + col], bb = cs[256 + 64 + col + 1];
        *(uint32_t*)(kdstA + col) =
            pkhf((acc[nt][0]-mukA)*rskA*ga + ba, (acc[nt][1]-mukA)*rskA*gb + bb);
        *(uint32_t*)(kdstB + col) =
            pkhf((acc[nt][2]-mukB)*rskB*ga + ba, (acc[nt][3]-mukB)*rskB*gb + bb);
    }
}

// ============================================================
// Kernel 2: fp16 mma.sync flash attention, bulk-copy K/V tiles,
// P entirely in registers (S c-frag -> PV a-frag identity).
// ============================================================
__device__ __forceinline__ void issue_tile(char* smem, int t, int b){
    if (t < NTK){
        int st = t & 1;
        uint32_t mbar = cvta_s(smem + OFF_MB + st*8);
        uint32_t kdst = cvta_s(smem + OFF_ST + st*STG);
        uint32_t vdst = kdst + KIMG_TILE_B;
        asm volatile("mbarrier.arrive.expect_tx.shared.b64 _, [%0], %1;"
            :: "r"(mbar), "r"(35328u) : "memory");
        const char* ksrc = (const char*)(g_kimg + (size_t)b*KIMG_BATCH_H) + (size_t)t*KIMG_TILE_B;
        const char* vsrc = (const char*)g_vimg + (size_t)t*VIMG_TILE_B;
        asm volatile("cp.async.bulk.shared::cta.global.mbarrier::complete_tx::bytes [%0], [%1], %2, [%3];"
            :: "r"(kdst), "l"(ksrc), "r"((uint32_t)KIMG_TILE_B), "r"(mbar) : "memory");
        asm volatile("cp.async.bulk.shared::cta.global.mbarrier::complete_tx::bytes [%0], [%1], %2, [%3];"
            :: "r"(vdst), "l"(vsrc), "r"((uint32_t)VIMG_TILE_B), "r"(mbar) : "memory");
    }
}

__global__ __launch_bounds__(256, 1) void attn_mma(
    const float* __restrict__ x,
    const float* __restrict__ Win,
    float* __restrict__ out)
{
    extern __shared__ char smem[];
    const int tid = threadIdx.x;
    const int wid = tid >> 5, lane = tid & 31;
    const int gid = lane >> 2, tig = lane & 3;
    const int b = blockIdx.y;
    const int n0 = blockIdx.x * BR;
    const int r0 = wid * 16;
    const float scale = 0.022360679774997897f;

    // Q prologue (regular cp.async)
#pragma unroll
    for (int j = 0; j < 4; j++){
        int c = tid + j*256;
        int row = c >> 3, ch = c & 7;
        int g = imin(n0 + row, NN-1);
        const __half* src = g_qf + ((size_t)b*NN + g)*E + ch*8;
        cpa16(cvta_s(smem + OFF_Q + row*144 + ch*16), src);
    }
    CP_COMMIT();

    if (tid == 0){
        mbar_init(cvta_s(smem + OFF_MB), 1);
        mbar_init(cvta_s(smem + OFF_MB + 8), 1);
    }
    __syncthreads();
    if (tid == 0){
        issue_tile(smem, 0, b);
        issue_tile(smem, 1, b);
    }
    asm volatile("cp.async.wait_group 0;");
    __syncthreads();

    float dacc[48][4];
#pragma unroll
    for (int nt = 0; nt < 48; nt++)
#pragma unroll
        for (int c = 0; c < 4; c++) dacc[nt][c] = 0.f;
    float lA = 0.f, lB = 0.f;

    const uint32_t* qf_s = (const uint32_t*)(smem + OFF_Q);

    for (int t = 0; t < NTK; t++){
        const int st = t & 1;
        mbar_wait(cvta_s(smem + OFF_MB + st*8), (t >> 1) & 1);

        // ---- S = Q.K (16 MMAs/warp)
        float sacc[4][4];
#pragma unroll
        for (int nt = 0; nt < 4; nt++)
#pragma unroll
            for (int c = 0; c < 4; c++) sacc[nt][c] = 0.f;
        {
            const uint32_t* kh = (const uint32_t*)(smem + OFF_ST + st*STG);
#pragma unroll
            for (int ks = 0; ks < 4; ks++){
                int qa = (r0 + gid)*36 + ks*8 + tig;
                int qb = qa + 8*36;
                uint32_t ah[4] = { qf_s[qa], qf_s[qb], qf_s[qa+4], qf_s[qb+4] };
#pragma unroll
                for (int nt = 0; nt < 4; nt++){
                    int kb = (nt*8 + gid)*36 + ks*8 + tig;
                    uint32_t bh[2] = { kh[kb], kh[kb+4] };
                    mma16816h(sacc[nt], ah, bh);
                }
            }
        }

        // ---- exp in registers (overwrite sacc with masked p)
#pragma unroll
        for (int nt = 0; nt < 4; nt++){
            int colg = t*BC + nt*8 + tig*2;
            bool m0 = colg < NN, m1 = (colg + 1) < NN;
            float p0 = m0 ? fexp(sacc[nt][0]*scale) : 0.f;
            float p1 = m1 ? fexp(sacc[nt][1]*scale) : 0.f;
            float p2 = m0 ? fexp(sacc[nt][2]*scale) : 0.f;
            float p3 = m1 ? fexp(sacc[nt][3]*scale) : 0.f;
            lA += p0 + p1; lB += p2 + p3;
            sacc[nt][0] = p0; sacc[nt][1] = p1;
            sacc[nt][2] = p2; sacc[nt][3] = p3;
        }

        // ---- PV: P a-frags directly from sacc (c-frag == a-frag identity)
        {
            const uint32_t* vh = (const uint32_t*)(smem + OFF_ST + st*STG + KIMG_TILE_B);
#pragma unroll
            for (int ks = 0; ks < 2; ks++){
                uint32_t pa[4] = {
                    pkhf(sacc[2*ks][0],   sacc[2*ks][1]),
                    pkhf(sacc[2*ks][2],   sacc[2*ks][3]),
                    pkhf(sacc[2*ks+1][0], sacc[2*ks+1][1]),
                    pkhf(sacc[2*ks+1][2], sacc[2*ks+1][3])
                };
#pragma unroll
                for (int nt = 0; nt < 48; nt++){
                    int vb = (nt*8 + gid)*20 + ks*8 + tig;
                    uint32_t bh[2] = { vh[vb], vh[vb+4] };
                    mma16816h(dacc[nt], pa, bh);
                }
            }
        }
        __syncthreads();                 // all warps done with stage st
        if (tid == 0) issue_tile(smem, t + 2, b);
    }

    // ---- epilogue (unchanged from R11/R12)
    lA += __shfl_xor_sync(0xffffffffu, lA, 1);
    lA += __shfl_xor_sync(0xffffffffu, lA, 2);
    lB += __shfl_xor_sync(0xffffffffu, lB, 1);
    lB += __shfl_xor_sync(0xffffffffu, lB, 2);
    const float invA = 1.f / lA;
    const float invB = 1.f / lB;

    const int nA = imin(n0 + r0 + gid, NN-1);
    const int nB = imin(n0 + r0 + gid + 8, NN-1);
    float q16A[DD], q16B[DD];
    {
        const float* xa = x + ((size_t)b*NN + nA)*TD + (TT-1)*DD;
        const float* xb = x + ((size_t)b*NN + nB)*TD + (TT-1)*DD;
#pragma unroll
        for (int dp = 0; dp < DD; dp++){
            float sa = 0.f, sb = 0.f;
#pragma unroll
            for (int d = 0; d < DD; d++){
                float w = Win[d*DD + dp];
                sa = fmaf(xa[d], w, sa);
                sb = fmaf(xb[d], w, sb);
            }
            q16A[dp] = sa; q16B[dp] = sb;
        }
    }

    float wAr[TT], wBr[TT];
#pragma unroll
    for (int t2 = 0; t2 < TT; t2++){
        int nt0 = 2*t2, nt1 = nt0 + 1;
        float aA = q16A[tig*2]   * dacc[nt0][0] + q16A[tig*2+1]   * dacc[nt0][1]
                 + q16A[8+tig*2] * dacc[nt1][0] + q16A[9+tig*2]   * dacc[nt1][1];
        float aB = q16B[tig*2]   * dacc[nt0][2] + q16B[tig*2+1]   * dacc[nt0][3]
                 + q16B[8+tig*2] * dacc[nt1][2] + q16B[9+tig*2]   * dacc[nt1][3];
        aA += __shfl_xor_sync(0xffffffffu, aA, 1);
        aA += __shfl_xor_sync(0xffffffffu, aA, 2);
        aB += __shfl_xor_sync(0xffffffffu, aB, 1);
        aB += __shfl_xor_sync(0xffffffffu, aB, 2);
        wAr[t2] = aA * invA;
        wBr[t2] = aB * invB;
    }
    {
        float mA = -1e30f, mB = -1e30f;
#pragma unroll
        for (int t2 = 0; t2 < TT; t2++){ mA = fmaxf(mA, wAr[t2]); mB = fmaxf(mB, wBr[t2]); }
        float sA = 0.f, sB = 0.f;
#pragma unroll
        for (int t2 = 0; t2 < TT; t2++){
            float eA = __expf(wAr[t2] - mA); wAr[t2] = eA; sA += eA;
            float eB = __expf(wBr[t2] - mB); wBr[t2] = eB; sB += eB;
        }
        float iA = 1.f / sA, iB = 1.f / sB;
#pragma unroll
        for (int t2 = 0; t2 < TT; t2++){ wAr[t2] *= iA; wBr[t2] *= iB; }
    }

    const bool vA = (n0 + r0 + gid) < NN;
    const bool vB = (n0 + r0 + gid + 8) < NN;
    float* orowA = out + ((size_t)b*NN + nA)*TD;
    float* orowB = out + ((size_t)b*NN + nB)*TD;
#pragma unroll
    for (int nt = 0; nt < 48; nt++){
        int col = nt*8 + tig*2;
        int t2 = nt >> 1;
        if (vA){
            float2 v; v.x = fmaf(dacc[nt][0], invA, wAr[t2]);
            v.y = fmaf(dacc[nt][1], invA, wAr[t2]);
            *(float2*)(orowA + col) = v;
        }
        if (vB){
            float2 v; v.x = fmaf(dacc[nt][2], invB, wBr[t2]);
            v.y = fmaf(dacc[nt][3], invB, wBr[t2]);
            *(float2*)(orowB + col) = v;
        }
    }
}

// ============================================================
extern "C" void kernel_launch(void* const* d_in, const int* in_sizes, int n_in,
                              void* d_out, int out_size)
{
    (void)in_sizes; (void)n_in; (void)out_size;
    const float* x     = (const float*)d_in[0];
    const float* Wq    = (const float*)d_in[1];
    const float* bq    = (const float*)d_in[2];
    const float* Wk    = (const float*)d_in[3];
    const float* bk    = (const float*)d_in[4];
    const float* g0    = (const float*)d_in[5];
    const float* beta0 = (const float*)d_in[6];
    const float* g1    = (const float*)d_in[7];
    const float* beta1 = (const float*)d_in[8];
    const float* nrm   = (const float*)d_in[9];
    const float* Win   = (const float*)d_in[10];
    float* out = (float*)d_out;

    cudaFuncSetAttribute(k1_tc,    cudaFuncAttributeMaxDynamicSharedMemorySize, K1_SMEM);
    cudaFuncSetAttribute(attn_mma, cudaFuncAttributeMaxDynamicSharedMemorySize, SMEM_ATT);

    prep_vt<<<(63*384*32 + 255)/256, 256>>>(nrm);
    prep_x<<<((B*NN*TD)/4 + 255)/256, 256>>>(x);
    prep_wt<<<(3*128*136 + 255)/256, 256>>>(Wq, Wk);

    k1_tc<<<(B*NN)/K1M, 256, K1_SMEM>>>(bq, bk, g0, beta0, g1, beta1);

    dim3 grid((NN + BR - 1)/BR, B);
    attn_mma<<<grid, 256, SMEM_ATT>>>(x, Win, out);
}

// round 14
// speedup vs baseline: 3.3724x; 1.1078x over previous
#include <cuda_runtime.h>
#include <cuda_fp16.h>
#include <cstdint>

#define B    32
#define NN   2000
#define TD   384
#define E    64
#define TT   24
#define DD   16

#define BR   128
#define NTK  32                          // 32 tiles x 64 kv (padded to 2048)

// ---- K/V gmem tile-image geometry (exact smem images, 72-half rows)
#define KIMG_TILE_H   4608               // 64 rows x 72 halves
#define KIMG_TILE_B   9216
#define KIMG_BATCH_H  147456             // 32 tiles
#define VIMG_TILE_H   27648              // 384 rows x 72 halves
#define VIMG_TILE_B   55296

// ---- attn smem byte layout
#define OFF_Q   0                        // 128 rows x 144B = 18432
#define OFF_MB  18432                    // 2 mbarriers
#define OFF_ST  18944                    // 2 stages x (K 9216 + V 55296)
#define STG     64512
#define SMEM_ATT (OFF_ST + 2*STG)        // 147968

// ---- k1 tensor-GEMM layout
#define K1M     128
#define K1_XST  68
#define K1_XTILE 34816
#define K1_OFF_X 0
#define K1_OFF_W 69632
#define K1_OFF_C 174080
#define K1_SMEM  175616

#define SCALE_S 0.022360679774997897f    // 1/sqrt(2000)

typedef unsigned long long u64;

__device__ __align__(16) __half g_qf[B*NN*E];        // pre-scaled by SCALE_S
__device__ __align__(16) __half g_kimg[B*KIMG_BATCH_H];
__device__ __align__(16) __half g_vimg[NTK*VIMG_TILE_H];
__device__ __align__(16) __half g_xh[B*NN*TD];
__device__ __align__(16) __half g_wt[3*128*136];

// =================== helpers ===================
__device__ __forceinline__ uint32_t cvta_s(const void* p){
    return (uint32_t)__cvta_generic_to_shared(p);
}
__device__ __forceinline__ void cpa16(uint32_t d, const void* s){
    asm volatile("cp.async.cg.shared.global [%0],[%1],16;" :: "r"(d), "l"(s));
}
#define CP_COMMIT() asm volatile("cp.async.commit_group;")

__device__ __forceinline__ void mma16816h(float* d, const uint32_t* a, const uint32_t* b){
    asm volatile("mma.sync.aligned.m16n8k16.row.col.f32.f16.f16.f32 "
        "{%0,%1,%2,%3},{%4,%5,%6,%7},{%8,%9},{%0,%1,%2,%3};"
        : "+f"(d[0]), "+f"(d[1]), "+f"(d[2]), "+f"(d[3])
        : "r"(a[0]), "r"(a[1]), "r"(a[2]), "r"(a[3]), "r"(b[0]), "r"(b[1]));
}

__device__ __forceinline__ int imin(int a, int b){ return a < b ? a : b; }
__device__ __forceinline__ uint32_t pkhf(float a, float b){
    __half2 h = __floats2half2_rn(a, b);
    return *(uint32_t*)&h;
}

__device__ __forceinline__ void mbar_init(uint32_t a, uint32_t cnt){
    asm volatile("mbarrier.init.shared.b64 [%0], %1;" :: "r"(a), "r"(cnt) : "memory");
}
__device__ __forceinline__ void mbar_wait(uint32_t a, uint32_t parity){
    uint32_t done;
    asm volatile("{.reg .pred p; mbarrier.try_wait.parity.acquire.cta.shared::cta.b64 p, [%1], %2; selp.b32 %0,1,0,p;}"
        : "=r"(done) : "r"(a), "r"(parity) : "memory");
    if (!done)
        asm volatile("{.reg .pred P1; WL%=: mbarrier.try_wait.parity.acquire.cta.shared::cta.b64 P1, [%0], %1, 0x989680;"
                     "@P1 bra.uni WD%=; bra.uni WL%=; WD%=: }" :: "r"(a), "r"(parity) : "memory");
}

// ============================================================
// prep kernels
// ============================================================
__global__ __launch_bounds__(256) void prep_vt(const float* __restrict__ normal){
    int idx = blockIdx.x*256 + threadIdx.x;      // 32*384*64 = 786432
    if (idx < NTK*384*64){
        int t = idx / (384*64);
        int rem = idx - t*(384*64);
        int n = rem >> 6, j = rem & 63;
        int kv = t*64 + j;
        float v = (kv < NN) ? normal[(size_t)kv*TD + n] : 0.f;
        g_vimg[(size_t)t*VIMG_TILE_H + n*72 + j] = __float2half_rn(v);
    }
}

__global__ __launch_bounds__(256) void prep_x(const float* __restrict__ x){
    int idx = blockIdx.x*256 + threadIdx.x;
    if (idx < (B*NN*TD)/4){
        float4 v = ((const float4*)x)[idx];
        uint2 o;
        o.x = pkhf(v.x, v.y);
        o.y = pkhf(v.z, v.w);
        ((uint2*)g_xh)[idx] = o;
    }
}

__global__ __launch_bounds__(256) void prep_wt(const float* __restrict__ Wq,
                                               const float* __restrict__ Wk){
    int idx = blockIdx.x*256 + threadIdx.x;
    if (idx < 3*128*136){
        int c = idx / (128*136);
        int rem = idx - c*(128*136);
        int n = rem / 136, kk = rem - n*136;
        float v = 0.f;
        if (kk < 128){
            int k = c*128 + kk;
            v = (n < 64) ? Wq[k*64 + n] : Wk[k*64 + (n - 64)];
        }
        g_wt[idx] = __float2half_rn(v);
    }
}

// ============================================================
// Kernel 1: y = xh @ W (fp16 HMMA), +bias, LN -> g_qf (pre-scaled) / g_kimg
// ============================================================
__device__ __forceinline__ void k1_prefx(char* sm, int tid, long base, int c, int s){
#pragma unroll
    for (int j = 0; j < 8; j++){
        int idx = tid + j*256;
        int row = idx >> 4, ch = idx & 15;
        const __half* src = g_xh + (base + row)*(size_t)TD + c*128 + ch*8;
        cpa16(cvta_s(sm + K1_OFF_X + s*K1_XTILE + row*272 + ch*16), src);
    }
    CP_COMMIT();
}

__global__ __launch_bounds__(256, 1) void k1_tc(
    const float* __restrict__ bq, const float* __restrict__ bk,
    const float* __restrict__ g0, const float* __restrict__ beta0,
    const float* __restrict__ g1, const float* __restrict__ beta1)
{
    extern __shared__ char sm[];
    const int tid = threadIdx.x;
    const int wid = tid >> 5, lane = tid & 31;
    const int gid = lane >> 2, tig = lane & 3;
    const int r0 = wid * 16;
    const long base = (long)blockIdx.x * K1M;

    float* cs = (float*)(sm + K1_OFF_C);
    if (tid < 128){
        cs[tid]       = (tid < 64) ? bq[tid] : bk[tid - 64];
        cs[128 + tid] = (tid < 64) ? g0[tid] : g1[tid - 64];
        cs[256 + tid] = (tid < 64) ? beta0[tid] : beta1[tid - 64];
    }

    k1_prefx(sm, tid, base, 0, 0);
    {
#pragma unroll
        for (int j = 0; j < 26; j++){
            int i = tid + j*256;
            if (i < 6528)
                cpa16(cvta_s(sm + K1_OFF_W + i*16), (const char*)g_wt + i*16);
        }
        CP_COMMIT();
    }
    k1_prefx(sm, tid, base, 1, 1);

    float acc[16][4];
#pragma unroll
    for (int nt = 0; nt < 16; nt++)
#pragma unroll
        for (int j = 0; j < 4; j++) acc[nt][j] = 0.f;

#pragma unroll
    for (int c = 0; c < 3; c++){
        if (c < 2) asm volatile("cp.async.wait_group 1;");
        else       asm volatile("cp.async.wait_group 0;");
        __syncthreads();
        const uint32_t* xs  = (const uint32_t*)(sm + K1_OFF_X + (c & 1)*K1_XTILE);
        const uint32_t* wsp = (const uint32_t*)(sm + K1_OFF_W + c*K1_XTILE);
#pragma unroll
        for (int ks = 0; ks < 8; ks++){
            int qa = (r0 + gid)*K1_XST + ks*8 + tig;
            int qb = qa + 8*K1_XST;
            uint32_t a[4] = { xs[qa], xs[qb], xs[qa+4], xs[qb+4] };
#pragma unroll
            for (int nt = 0; nt < 16; nt++){
                int kb = (nt*8 + gid)*K1_XST + ks*8 + tig;
                uint32_t bfr[2] = { wsp[kb], wsp[kb+4] };
                mma16816h(acc[nt], a, bfr);
            }
        }
        __syncthreads();
        if (c == 0){ k1_prefx(sm, tid, base, 2, 0); }
    }

    const int c0 = tig*2;
#pragma unroll
    for (int nt = 0; nt < 16; nt++){
        int col = (nt < 8) ? nt*8 + c0 : 64 + (nt - 8)*8 + c0;
        float b0 = cs[col], b1 = cs[col + 1];
        acc[nt][0] += b0; acc[nt][1] += b1;
        acc[nt][2] += b0; acc[nt][3] += b1;
    }
    float sqA=0,ssA=0,skA=0,sskA=0, sqB=0,ssB=0,skB=0,sskB=0;
#pragma unroll
    for (int nt = 0; nt < 8; nt++){
        sqA += acc[nt][0] + acc[nt][1];
        ssA += acc[nt][0]*acc[nt][0] + acc[nt][1]*acc[nt][1];
        sqB += acc[nt][2] + acc[nt][3];
        ssB += acc[nt][2]*acc[nt][2] + acc[nt][3]*acc[nt][3];
    }
#pragma unroll
    for (int nt = 8; nt < 16; nt++){
        skA += acc[nt][0] + acc[nt][1];
        sskA += acc[nt][0]*acc[nt][0] + acc[nt][1]*acc[nt][1];
        skB += acc[nt][2] + acc[nt][3];
        sskB += acc[nt][2]*acc[nt][2] + acc[nt][3]*acc[nt][3];
    }
#pragma unroll
    for (int off = 1; off <= 2; off <<= 1){
        sqA += __shfl_xor_sync(0xffffffffu, sqA, off);
        ssA += __shfl_xor_sync(0xffffffffu, ssA, off);
        skA += __shfl_xor_sync(0xffffffffu, skA, off);
        sskA += __shfl_xor_sync(0xffffffffu, sskA, off);
        sqB += __shfl_xor_sync(0xffffffffu, sqB, off);
        ssB += __shfl_xor_sync(0xffffffffu, ssB, off);
        skB += __shfl_xor_sync(0xffffffffu, skB, off);
        sskB += __shfl_xor_sync(0xffffffffu, sskB, off);
    }
    const float inv64 = 1.f/64.f;
    float muqA = sqA*inv64, rsqA = rsqrtf(ssA*inv64 - muqA*muqA + 1e-5f) * SCALE_S;
    float muqB = sqB*inv64, rsqB = rsqrtf(ssB*inv64 - muqB*muqB + 1e-5f) * SCALE_S;
    float mukA = skA*inv64, rskA = rsqrtf(sskA*inv64 - mukA*mukA + 1e-5f);
    float mukB = skB*inv64, rskB = rsqrtf(sskB*inv64 - mukB*mukB + 1e-5f);

    const int grA = (int)(base + r0 + gid);
    const int grB = grA + 8;
    const int bA = grA / NN, nAq = grA - bA*NN;
    const int bB = grB / NN, nBq = grB - bB*NN;
    __half* kdstA = g_kimg + (size_t)bA*KIMG_BATCH_H + (nAq >> 6)*KIMG_TILE_H + (nAq & 63)*72;
    __half* kdstB = g_kimg + (size_t)bB*KIMG_BATCH_H + (nBq >> 6)*KIMG_TILE_H + (nBq & 63)*72;

    // q: gamma*scale folded into rsq; beta scaled too
#pragma unroll
    for (int nt = 0; nt < 8; nt++){
        int col = nt*8 + c0;
        float ga = cs[128 + col], gb = cs[128 + col + 1];
        float ba = cs[256 + col] * SCALE_S, bb = cs[256 + col + 1] * SCALE_S;
        *(uint32_t*)(g_qf + (size_t)grA*E + col) =
            pkhf((acc[nt][0]-muqA)*rsqA*ga + ba, (acc[nt][1]-muqA)*rsqA*gb + bb);
        *(uint32_t*)(g_qf + (size_t)grB*E + col) =
            pkhf((acc[nt][2]-muqB)*rsqB*ga + ba, (acc[nt][3]-muqB)*rsqB*gb + bb);
    }
#pragma unroll
    for (int nt = 8; nt < 16; nt++){
        int col = (nt - 8)*8 + c0;
        float ga = cs[128 + 64 + col], gb = cs[128 + 64 + col + 1];
        float ba = cs[256 + 64 + col], bb = cs[256 + 64 + col + 1];
        *(uint32_t*)(kdstA + col) =
            pkhf((acc[nt][0]-mukA)*rskA*ga + ba, (acc[nt][1]-mukA)*rskA*gb + bb);
        *(uint32_t*)(kdstB + col) =
            pkhf((acc[nt][2]-mukB)*rskB*ga + ba, (acc[nt][3]-mukB)*rskB*gb + bb);
    }
}

// ============================================================
// Kernel 2: fp16 mma.sync flash attention, 64-kv bulk stages,
// P in registers, __expf softmax (scale pre-folded into q).
// ============================================================
__device__ __forceinline__ void issue_tile(char* smem, int t, int b){
    if (t < NTK){
        int st = t & 1;
        uint32_t mbar = cvta_s(smem + OFF_MB + st*8);
        uint32_t kdst = cvta_s(smem + OFF_ST + st*STG);
        uint32_t vdst = kdst + KIMG_TILE_B;
        asm volatile("mbarrier.arrive.expect_tx.shared.b64 _, [%0], %1;"
            :: "r"(mbar), "r"((uint32_t)STG) : "memory");
        const char* ksrc = (const char*)(g_kimg + (size_t)b*KIMG_BATCH_H) + (size_t)t*KIMG_TILE_B;
        const char* vsrc = (const char*)g_vimg + (size_t)t*VIMG_TILE_B;
        asm volatile("cp.async.bulk.shared::cta.global.mbarrier::complete_tx::bytes [%0], [%1], %2, [%3];"
            :: "r"(kdst), "l"(ksrc), "r"((uint32_t)KIMG_TILE_B), "r"(mbar) : "memory");
        asm volatile("cp.async.bulk.shared::cta.global.mbarrier::complete_tx::bytes [%0], [%1], %2, [%3];"
            :: "r"(vdst), "l"(vsrc), "r"((uint32_t)VIMG_TILE_B), "r"(mbar) : "memory");
    }
}

__global__ __launch_bounds__(256, 1) void attn_mma(
    const float* __restrict__ x,
    const float* __restrict__ Win,
    float* __restrict__ out)
{
    extern __shared__ char smem[];
    const int tid = threadIdx.x;
    const int wid = tid >> 5, lane = tid & 31;
    const int gid = lane >> 2, tig = lane & 3;
    const int b = blockIdx.y;
    const int n0 = blockIdx.x * BR;
    const int r0 = wid * 16;

    // Q prologue
#pragma unroll
    for (int j = 0; j < 4; j++){
        int c = tid + j*256;
        int row = c >> 3, ch = c & 7;
        int g = imin(n0 + row, NN-1);
        const __half* src = g_qf + ((size_t)b*NN + g)*E + ch*8;
        cpa16(cvta_s(smem + OFF_Q + row*144 + ch*16), src);
    }
    CP_COMMIT();

    if (tid == 0){
        mbar_init(cvta_s(smem + OFF_MB), 1);
        mbar_init(cvta_s(smem + OFF_MB + 8), 1);
    }
    __syncthreads();
    if (tid == 0){
        issue_tile(smem, 0, b);
        issue_tile(smem, 1, b);
    }
    asm volatile("cp.async.wait_group 0;");
    __syncthreads();

    float dacc[48][4];
#pragma unroll
    for (int nt = 0; nt < 48; nt++)
#pragma unroll
        for (int c = 0; c < 4; c++) dacc[nt][c] = 0.f;
    float lA = 0.f, lB = 0.f;

    const uint32_t* qf_s = (const uint32_t*)(smem + OFF_Q);

    for (int t = 0; t < NTK; t++){
        const int st = t & 1;
        mbar_wait(cvta_s(smem + OFF_MB + st*8), (t >> 1) & 1);

        const uint32_t* kh = (const uint32_t*)(smem + OFF_ST + st*STG);
        const uint32_t* vh = (const uint32_t*)(smem + OFF_ST + st*STG + KIMG_TILE_B);

#pragma unroll
        for (int sub = 0; sub < 2; sub++){
            // ---- S = Q.K (16 MMAs/warp); q pre-scaled so S is final exp arg
            float sacc[4][4];
#pragma unroll
            for (int nt = 0; nt < 4; nt++)
#pragma unroll
                for (int c = 0; c < 4; c++) sacc[nt][c] = 0.f;
#pragma unroll
            for (int ks = 0; ks < 4; ks++){
                int qa = (r0 + gid)*36 + ks*8 + tig;
                int qb = qa + 8*36;
                uint32_t ah[4] = { qf_s[qa], qf_s[qb], qf_s[qa+4], qf_s[qb+4] };
#pragma unroll
                for (int nt = 0; nt < 4; nt++){
                    int kb = (sub*32 + nt*8 + gid)*36 + ks*8 + tig;
                    uint32_t bh[2] = { kh[kb], kh[kb+4] };
                    mma16816h(sacc[nt], ah, bh);
                }
            }

            // ---- exp in registers (MUFU), masked
#pragma unroll
            for (int nt = 0; nt < 4; nt++){
                int colg = t*64 + sub*32 + nt*8 + tig*2;
                bool m0 = colg < NN, m1 = (colg + 1) < NN;
                float p0 = m0 ? __expf(sacc[nt][0]) : 0.f;
                float p1 = m1 ? __expf(sacc[nt][1]) : 0.f;
                float p2 = m0 ? __expf(sacc[nt][2]) : 0.f;
                float p3 = m1 ? __expf(sacc[nt][3]) : 0.f;
                lA += p0 + p1; lB += p2 + p3;
                sacc[nt][0] = p0; sacc[nt][1] = p1;
                sacc[nt][2] = p2; sacc[nt][3] = p3;
            }

            // ---- PV: P a-frags from sacc, V at k-offset sub*16 uints
#pragma unroll
            for (int ks = 0; ks < 2; ks++){
                uint32_t pa[4] = {
                    pkhf(sacc[2*ks][0],   sacc[2*ks][1]),
                    pkhf(sacc[2*ks][2],   sacc[2*ks][3]),
                    pkhf(sacc[2*ks+1][0], sacc[2*ks+1][1]),
                    pkhf(sacc[2*ks+1][2], sacc[2*ks+1][3])
                };
#pragma unroll
                for (int nt = 0; nt < 48; nt++){
                    int vb = (nt*8 + gid)*36 + sub*16 + ks*8 + tig;
                    uint32_t bh[2] = { vh[vb], vh[vb+4] };
                    mma16816h(dacc[nt], pa, bh);
                }
            }
        }
        __syncthreads();                 // all warps done with stage st
        if (tid == 0) issue_tile(smem, t + 2, b);
    }

    // ---- epilogue
    lA += __shfl_xor_sync(0xffffffffu, lA, 1);
    lA += __shfl_xor_sync(0xffffffffu, lA, 2);
    lB += __shfl_xor_sync(0xffffffffu, lB, 1);
    lB += __shfl_xor_sync(0xffffffffu, lB, 2);
    const float invA = 1.f / lA;
    const float invB = 1.f / lB;

    const int nA = imin(n0 + r0 + gid, NN-1);
    const int nB = imin(n0 + r0 + gid + 8, NN-1);
    float q16A[DD], q16B[DD];
    {
        const float* xa = x + ((size_t)b*NN + nA)*TD + (TT-1)*DD;
        const float* xb = x + ((size_t)b*NN + nB)*TD + (TT-1)*DD;
#pragma unroll
        for (int dp = 0; dp < DD; dp++){
            float sa = 0.f, sb = 0.f;
#pragma unroll
            for (int d = 0; d < DD; d++){
                float w = Win[d*DD + dp];
                sa = fmaf(xa[d], w, sa);
                sb = fmaf(xb[d], w, sb);
            }
            q16A[dp] = sa; q16B[dp] = sb;
        }
    }

    float wAr[TT], wBr[TT];
#pragma unroll
    for (int t2 = 0; t2 < TT; t2++){
        int nt0 = 2*t2, nt1 = nt0 + 1;
        float aA = q16A[tig*2]   * dacc[nt0][0] + q16A[tig*2+1]   * dacc[nt0][1]
                 + q16A[8+tig*2] * dacc[nt1][0] + q16A[9+tig*2]   * dacc[nt1][1];
        float aB = q16B[tig*2]   * dacc[nt0][2] + q16B[tig*2+1]   * dacc[nt0][3]
                 + q16B[8+tig*2] * dacc[nt1][2] + q16B[9+tig*2]   * dacc[nt1][3];
        aA += __shfl_xor_sync(0xffffffffu, aA, 1);
        aA += __shfl_xor_sync(0xffffffffu, aA, 2);
        aB += __shfl_xor_sync(0xffffffffu, aB, 1);
        aB += __shfl_xor_sync(0xffffffffu, aB, 2);
        wAr[t2] = aA * invA;
        wBr[t2] = aB * invB;
    }
    {
        float mA = -1e30f, mB = -1e30f;
#pragma unroll
        for (int t2 = 0; t2 < TT; t2++){ mA = fmaxf(mA, wAr[t2]); mB = fmaxf(mB, wBr[t2]); }
        float sA = 0.f, sB = 0.f;
#pragma unroll
        for (int t2 = 0; t2 < TT; t2++){
            float eA = __expf(wAr[t2] - mA); wAr[t2] = eA; sA += eA;
            float eB = __expf(wBr[t2] - mB); wBr[t2] = eB; sB += eB;
        }
        float iA = 1.f / sA, iB = 1.f / sB;
#pragma unroll
        for (int t2 = 0; t2 < TT; t2++){ wAr[t2] *= iA; wBr[t2] *= iB; }
    }

    const bool vA = (n0 + r0 + gid) < NN;
    const bool vB = (n0 + r0 + gid + 8) < NN;
    float* orowA = out + ((size_t)b*NN + nA)*TD;
    float* orowB = out + ((size_t)b*NN + nB)*TD;
#pragma unroll
    for (int nt = 0; nt < 48; nt++){
        int col = nt*8 + tig*2;
        int t2 = nt >> 1;
        if (vA){
            float2 v; v.x = fmaf(dacc[nt][0], invA, wAr[t2]);
            v.y = fmaf(dacc[nt][1], invA, wAr[t2]);
            *(float2*)(orowA + col) = v;
        }
        if (vB){
            float2 v; v.x = fmaf(dacc[nt][2], invB, wBr[t2]);
            v.y = fmaf(dacc[nt][3], invB, wBr[t2]);
            *(float2*)(orowB + col) = v;
        }
    }
}

// ============================================================
extern "C" void kernel_launch(void* const* d_in, const int* in_sizes, int n_in,
                              void* d_out, int out_size)
{
    (void)in_sizes; (void)n_in; (void)out_size;
    const float* x     = (const float*)d_in[0];
    const float* Wq    = (const float*)d_in[1];
    const float* bq    = (const float*)d_in[2];
    const float* Wk    = (const float*)d_in[3];
    const float* bk    = (const float*)d_in[4];
    const float* g0    = (const float*)d_in[5];
    const float* beta0 = (const float*)d_in[6];
    const float* g1    = (const float*)d_in[7];
    const float* beta1 = (const float*)d_in[8];
    const float* nrm   = (const float*)d_in[9];
    const float* Win   = (const float*)d_in[10];
    float* out = (float*)d_out;

    cudaFuncSetAttribute(k1_tc,    cudaFuncAttributeMaxDynamicSharedMemorySize, K1_SMEM);
    cudaFuncSetAttribute(attn_mma, cudaFuncAttributeMaxDynamicSharedMemorySize, SMEM_ATT);

    prep_vt<<<(NTK*384*64 + 255)/256, 256>>>(nrm);
    prep_x<<<((B*NN*TD)/4 + 255)/256, 256>>>(x);
    prep_wt<<<(3*128*136 + 255)/256, 256>>>(Wq, Wk);

    k1_tc<<<(B*NN)/K1M, 256, K1_SMEM>>>(bq, bk, g0, beta0, g1, beta1);

    dim3 grid((NN + BR - 1)/BR, B);
    attn_mma<<<grid, 256, SMEM_ATT>>>(x, Win, out);
}